// round 9
// baseline (speedup 1.0000x reference)
#include <cuda_runtime.h>
#include <cuda_bf16.h>
#include <math.h>
#include <stdint.h>

#define NN 100000
#define EE 1600000
#define HH 128
#define GG 256
#define LL 3
#define NB_SCAN ((NN + 1023) / 1024)   // 98
#define NTILES ((NN + 127) / 128)      // 782

// padded k-major bf16 tile in smem: 128 rows x 136 halves (272 B row pitch)
#define RPITCH 272
#define TILE_U4 2176   // 128 * 17 uint4

// ---------------- scratch (device globals; no allocation) ----------------
__device__ __align__(16) float g_h[NN * HH];
__device__ __align__(16) float g_t[NN * HH];
__device__ __align__(16) float g_r[NN * HH];
__device__ __align__(16) float g_tmp[NN * HH];
__device__ __align__(16) float g_out[GG * 16];
__device__ __align__(16) float g_F[HH * HH];
__device__ __align__(16) float g_c[HH];
__device__ __align__(16) uint4 g_Bhi[TILE_U4];   // W^T bf16 hi (padded k-major)
__device__ __align__(16) uint4 g_Blo[TILE_U4];   // W^T bf16 lo
// pre-split activation buffers (row-major, 16 uint4 = 128 bf16 per row), 2 ping-pong pairs
__device__ __align__(16) uint4 g_s0h[NN * 16];
__device__ __align__(16) uint4 g_s0l[NN * 16];
__device__ __align__(16) uint4 g_s1h[NN * 16];
__device__ __align__(16) uint4 g_s1l[NN * 16];
__device__ int    g_deg[NN];
__device__ int    g_incl[NN];
__device__ int    g_rowptr[NN + 1];
__device__ int    g_cursor[NN];
__device__ int    g_srcs[EE];
__device__ float4 g_ppf[EE];
__device__ int    g_bsum[128];
__device__ int    g_is64;

__device__ __forceinline__ float* getbuf(int id) {
    switch (id) {
        case 0: return g_h;
        case 1: return g_t;
        case 2: return g_r;
        default: return g_tmp;
    }
}
__device__ __forceinline__ uint4* gs_hi(int id) { return id ? g_s1h : g_s0h; }
__device__ __forceinline__ uint4* gs_lo(int id) { return id ? g_s1l : g_s0l; }

__device__ __forceinline__ int load_idx(const void* p, long long i, int is64) {
    if (is64) return (int)((const long long*)p)[i];
    return ((const int*)p)[i];
}

// ================= mma.sync helpers (baseline sm_80+ PTX) =================
__device__ __forceinline__ uint32_t smem_u32(const void* p) {
    uint32_t a;
    asm("{ .reg .u64 t; cvta.to.shared.u64 t, %1; cvt.u32.u64 %0, t; }" : "=r"(a) : "l"(p));
    return a;
}
__device__ __forceinline__ void ldm4(uint32_t* r, uint32_t addr) {
    asm volatile("ldmatrix.sync.aligned.m8n8.x4.shared.b16 {%0,%1,%2,%3}, [%4];"
        : "=r"(r[0]), "=r"(r[1]), "=r"(r[2]), "=r"(r[3]) : "r"(addr));
}
__device__ __forceinline__ void mma16816(float* d, const uint32_t* a, uint32_t b0, uint32_t b1) {
    asm volatile("mma.sync.aligned.m16n8k16.row.col.f32.bf16.bf16.f32 "
        "{%0,%1,%2,%3}, {%4,%5,%6,%7}, {%8,%9}, {%0,%1,%2,%3};"
        : "+f"(d[0]), "+f"(d[1]), "+f"(d[2]), "+f"(d[3])
        : "r"(a[0]), "r"(a[1]), "r"(a[2]), "r"(a[3]), "r"(b0), "r"(b1));
}

// split helpers
__device__ __forceinline__ void split1(float v, unsigned& h, unsigned& l) {
    __nv_bfloat16 hb = __float2bfloat16(v);
    float rem = v - __bfloat162float(hb);
    __nv_bfloat16 lb = __float2bfloat16(rem);
    h = (unsigned)__bfloat16_as_ushort(hb);
    l = (unsigned)__bfloat16_as_ushort(lb);
}
__device__ __forceinline__ void split8(const float* v, uint4& hi, uint4& lo) {
    unsigned hs[8], ls[8];
#pragma unroll
    for (int j = 0; j < 8; j++) split1(v[j], hs[j], ls[j]);
    hi = make_uint4(hs[0] | (hs[1] << 16), hs[2] | (hs[3] << 16), hs[4] | (hs[5] << 16), hs[6] | (hs[7] << 16));
    lo = make_uint4(ls[0] | (ls[1] << 16), ls[2] | (ls[3] << 16), ls[4] | (ls[5] << 16), ls[6] | (ls[7] << 16));
}
__device__ __forceinline__ void split4_u2(const float4& v, uint2& hi, uint2& lo) {
    unsigned h0, h1, h2, h3, l0, l1, l2, l3;
    split1(v.x, h0, l0); split1(v.y, h1, l1); split1(v.z, h2, l2); split1(v.w, h3, l3);
    hi = make_uint2(h0 | (h1 << 16), h2 | (h3 << 16));
    lo = make_uint2(l0 | (l1 << 16), l2 | (l3 << 16));
}

// ---------------- dtype detection ----------------
__global__ void k_detect(const void* ei) {
    __shared__ int s_nz;
    if (threadIdx.x == 0) s_nz = 0;
    __syncthreads();
    const int* w = (const int*)ei;
    int v = w[2 * threadIdx.x + 1];
    int v2 = w[2 * (threadIdx.x + 1024) + 1];
    if ((v | v2) != 0) atomicOr(&s_nz, 1);
    __syncthreads();
    if (threadIdx.x == 0) g_is64 = s_nz ? 0 : 1;
}

__global__ void k_init() {
    int i = blockIdx.x * blockDim.x + threadIdx.x;
    if (i < GG * 16) g_out[i] = 0.f;
    if (i < NN) g_deg[i] = 0;
}

__global__ void k_hist(const void* ei) {
    int e = blockIdx.x * blockDim.x + threadIdx.x;
    if (e < EE) {
        int d = load_idx(ei, (long long)EE + e, g_is64);
        atomicAdd(&g_deg[d], 1);
    }
}

__global__ void k_scan1() {
    __shared__ int s[1024];
    int tid = threadIdx.x;
    int i = blockIdx.x * 1024 + tid;
    int v = (i < NN) ? g_deg[i] : 0;
    s[tid] = v;
    __syncthreads();
    for (int off = 1; off < 1024; off <<= 1) {
        int a = (tid >= off) ? s[tid - off] : 0;
        __syncthreads();
        s[tid] += a;
        __syncthreads();
    }
    if (i < NN) g_incl[i] = s[tid];
    if (tid == 1023) g_bsum[blockIdx.x] = s[1023];
}

__global__ void k_scan2() {
    __shared__ int s[128];
    int tid = threadIdx.x;
    s[tid] = (tid < NB_SCAN) ? g_bsum[tid] : 0;
    __syncthreads();
    for (int off = 1; off < 128; off <<= 1) {
        int a = (tid >= off) ? s[tid - off] : 0;
        __syncthreads();
        s[tid] += a;
        __syncthreads();
    }
    if (tid < NB_SCAN) g_bsum[tid] = s[tid];
}

__global__ void k_fin() {
    int tid = threadIdx.x;
    int i = blockIdx.x * 1024 + tid;
    if (i < NN) {
        int off = blockIdx.x ? g_bsum[blockIdx.x - 1] : 0;
        int excl = g_incl[i] - g_deg[i] + off;
        g_rowptr[i] = excl;
        g_cursor[i] = excl;
    }
    if (i == 0) g_rowptr[NN] = EE;
}

__device__ __forceinline__ float dot3(float ax, float ay, float az, float bx, float by, float bz) {
    return ax * bx + ay * by + az * bz;
}
__device__ __forceinline__ float crossnorm(float ax, float ay, float az, float bx, float by, float bz) {
    float cx = ay * bz - az * by;
    float cy = az * bx - ax * bz;
    float cz = ax * by - ay * bx;
    return sqrtf(cx * cx + cy * cy + cz * cz);
}

__global__ void k_scatter(const void* ei, const float* pos) {
    int e = blockIdx.x * blockDim.x + threadIdx.x;
    if (e >= EE) return;
    int is64 = g_is64;
    int s = load_idx(ei, e, is64);
    int d = load_idx(ei, (long long)EE + e, is64);
    float pix = pos[3 * d], piy = pos[3 * d + 1], piz = pos[3 * d + 2];
    float pjx = pos[3 * s], pjy = pos[3 * s + 1], pjz = pos[3 * s + 2];
    float nin = sqrtf(pix * pix + piy * piy + piz * piz) + 1e-12f;
    float njn = sqrtf(pjx * pjx + pjy * pjy + pjz * pjz) + 1e-12f;
    float nix = pix / nin, niy = piy / nin, niz = piz / nin;
    float njx = pjx / njn, njy = pjy / njn, njz = pjz / njn;
    float dx = pjx - pix, dy = pjy - piy, dz = pjz - piz;
    float f0 = sqrtf(dx * dx + dy * dy + dz * dz);
    float f1 = atan2f(crossnorm(nix, niy, niz, dx, dy, dz), dot3(nix, niy, niz, dx, dy, dz));
    float f2 = atan2f(crossnorm(njx, njy, njz, dx, dy, dz), dot3(njx, njy, njz, dx, dy, dz));
    float f3 = atan2f(crossnorm(nix, niy, niz, njx, njy, njz), dot3(nix, niy, niz, njx, njy, njz));
    int slot = atomicAdd(&g_cursor[d], 1);
    g_srcs[slot] = s;
    g_ppf[slot] = make_float4(f0, f1, f2, f3);
}

// ---------------- g_F = A@B (128x128), g_c = v@B ----------------
__global__ void k_combine(const float* A, const float* B, const float* v) {
    int col = threadIdx.x;
    int row = blockIdx.x;
    if (row < 128) {
        float s = 0.f;
        for (int k = 0; k < 128; k++) s = fmaf(A[row * 128 + k], B[k * 128 + col], s);
        g_F[row * 128 + col] = s;
    } else {
        float s = 0.f;
        for (int k = 0; k < 128; k++) s = fmaf(v[k], B[k * 128 + col], s);
        g_c[col] = s;
    }
}

// ---------------- weight split: W[k][n] (or g_F) -> g_Bhi/g_Blo (padded k-major) ----------------
__global__ void k_split(const float* W, int wsel) {
    const float* src = wsel ? g_F : W;
    int i = blockIdx.x * blockDim.x + threadIdx.x;
    if (i >= 2048) return;
    int n = i >> 4, kg = i & 15;
    float v[8];
#pragma unroll
    for (int j = 0; j < 8; j++) v[j] = src[(kg * 8 + j) * 128 + n];
    uint4 hi, lo;
    split8(v, hi, lo);
    g_Bhi[n * 17 + kg] = hi;
    g_Blo[n * 17 + kg] = lo;
}

// ---------------- HMMA GEMM: Y = act(X @ W [+ bias|g_c] [+ deg*g_c]) ----------------
// Input: pre-split bf16 pair ip. Outputs: fp32 buf yid (if OF32) and/or split pair op (if OSPLIT).
// BMODE: 0 none, 1 bias (bias==nullptr -> g_c), 3 bias + deg*g_c
#define SM_BHI 0
#define SM_BLO 34816
#define SM_AHI 69632
#define SM_ALO 104448
#define SM_BYTES 139264

template <int BMODE, bool RELU, bool OF32, bool OSPLIT>
__global__ void __launch_bounds__(256, 1) k_mmagemm(int ip, const float* bias, int yid, int op, int nrows) {
    extern __shared__ char sm[];
    const uint4* Xhi = gs_hi(ip);
    const uint4* Xlo = gs_lo(ip);
    float* Y = getbuf(yid);
    ushort2* Ohi = (ushort2*)gs_hi(op);
    ushort2* Olo = (ushort2*)gs_lo(op);

    int tid = threadIdx.x;
    int wid = tid >> 5;
    int lane = tid & 31;

    // persistent weights into smem
    uint4* bhi_s = (uint4*)(sm + SM_BHI);
    uint4* blo_s = (uint4*)(sm + SM_BLO);
    for (int i = tid; i < TILE_U4; i += 256) {
        bhi_s[i] = g_Bhi[i];
        blo_s[i] = g_Blo[i];
    }

    const int mrow0 = (wid & 3) * 32;
    const int ncol0 = (wid >> 2) * 64;
    const int lrow = lane & 15;
    const int lkof = ((lane >> 4) << 3) * 2;

    uint32_t a_base_hi = smem_u32(sm + SM_AHI);
    uint32_t a_base_lo = smem_u32(sm + SM_ALO);
    uint32_t b_base_hi = smem_u32(sm + SM_BHI);
    uint32_t b_base_lo = smem_u32(sm + SM_BLO);

    for (int tile = blockIdx.x; tile < NTILES; tile += gridDim.x) {
        int row0 = tile * 128;
        __syncthreads();
        // verbatim copy of pre-split A tile into padded smem
        for (int i = tid; i < 2048; i += 256) {
            int row = i >> 4, grp = i & 15;
            int r = row0 + row;
            uint4 hi = make_uint4(0, 0, 0, 0), lo = make_uint4(0, 0, 0, 0);
            if (r < nrows) {
                hi = Xhi[(long long)r * 16 + grp];
                lo = Xlo[(long long)r * 16 + grp];
            }
            *(uint4*)(sm + SM_AHI + row * RPITCH + grp * 16) = hi;
            *(uint4*)(sm + SM_ALO + row * RPITCH + grp * 16) = lo;
        }
        __syncthreads();

        float d[2][8][4];
#pragma unroll
        for (int mt = 0; mt < 2; mt++)
#pragma unroll
            for (int nt = 0; nt < 8; nt++)
#pragma unroll
                for (int j = 0; j < 4; j++) d[mt][nt][j] = 0.f;

#pragma unroll
        for (int kk = 0; kk < 8; kk++) {
            int kb = kk * 32 + lkof;
            uint32_t ah[2][4], al[2][4];
#pragma unroll
            for (int mt = 0; mt < 2; mt++) {
                uint32_t off = (mrow0 + mt * 16 + lrow) * RPITCH + kb;
                ldm4(ah[mt], a_base_hi + off);
                ldm4(al[mt], a_base_lo + off);
            }
            uint32_t bh[4][4], bl[4][4];
#pragma unroll
            for (int np = 0; np < 4; np++) {
                uint32_t off = (ncol0 + np * 16 + lrow) * RPITCH + kb;
                ldm4(bh[np], b_base_hi + off);
                ldm4(bl[np], b_base_lo + off);
            }
#pragma unroll
            for (int mt = 0; mt < 2; mt++) {
#pragma unroll
                for (int np = 0; np < 4; np++) {
                    mma16816(d[mt][np * 2],     ah[mt], bh[np][0], bh[np][2]);
                    mma16816(d[mt][np * 2],     ah[mt], bl[np][0], bl[np][2]);
                    mma16816(d[mt][np * 2],     al[mt], bh[np][0], bh[np][2]);
                    mma16816(d[mt][np * 2 + 1], ah[mt], bh[np][1], bh[np][3]);
                    mma16816(d[mt][np * 2 + 1], ah[mt], bl[np][1], bl[np][3]);
                    mma16816(d[mt][np * 2 + 1], al[mt], bh[np][1], bh[np][3]);
                }
            }
        }

        int rbase = row0 + mrow0 + (lane >> 2);
        int cbase = ncol0 + 2 * (lane & 3);
#pragma unroll
        for (int mt = 0; mt < 2; mt++) {
            int r0 = rbase + mt * 16;
            int r1 = r0 + 8;
            float sc0 = 0.f, sc1 = 0.f;
            if (BMODE == 3) {
                if (r0 < nrows) sc0 = (float)g_deg[r0];
                if (r1 < nrows) sc1 = (float)g_deg[r1];
            }
#pragma unroll
            for (int nt = 0; nt < 8; nt++) {
                int c = cbase + nt * 8;
                float b0 = 0.f, b1 = 0.f, c0 = 0.f, c1 = 0.f;
                if (BMODE >= 1) {
                    const float* bp = (bias != nullptr) ? bias : g_c;
                    b0 = bp[c]; b1 = bp[c + 1];
                }
                if (BMODE == 3) { c0 = g_c[c]; c1 = g_c[c + 1]; }
                if (r0 < nrows) {
                    float v0 = d[mt][nt][0] + b0 + sc0 * c0;
                    float v1 = d[mt][nt][1] + b1 + sc0 * c1;
                    if (RELU) { v0 = fmaxf(v0, 0.f); v1 = fmaxf(v1, 0.f); }
                    if (OF32) *(float2*)&Y[(long long)r0 * 128 + c] = make_float2(v0, v1);
                    if (OSPLIT) {
                        unsigned h0, h1, l0, l1;
                        split1(v0, h0, l0); split1(v1, h1, l1);
                        long long idx = (long long)r0 * 64 + (c >> 1);
                        Ohi[idx] = make_ushort2((unsigned short)h0, (unsigned short)h1);
                        Olo[idx] = make_ushort2((unsigned short)l0, (unsigned short)l1);
                    }
                }
                if (r1 < nrows) {
                    float v2 = d[mt][nt][2] + b0 + sc1 * c0;
                    float v3 = d[mt][nt][3] + b1 + sc1 * c1;
                    if (RELU) { v2 = fmaxf(v2, 0.f); v3 = fmaxf(v3, 0.f); }
                    if (OF32) *(float2*)&Y[(long long)r1 * 128 + c] = make_float2(v2, v3);
                    if (OSPLIT) {
                        unsigned h2, h3, l2, l3;
                        split1(v2, h2, l2); split1(v3, h3, l3);
                        long long idx = (long long)r1 * 64 + (c >> 1);
                        Ohi[idx] = make_ushort2((unsigned short)h2, (unsigned short)h3);
                        Olo[idx] = make_ushort2((unsigned short)l2, (unsigned short)l3);
                    }
                }
            }
        }
    }
}

// ---------------- small GEMM (K=16 node in + heads); optional split output ----------------
template <int K, int M, int BMODE, bool RELU, bool OSPLIT>
__global__ void k_gemm(int xid, const float* Xext,
                       const float* W, const float* bias,
                       int yid, int op, int nrows) {
    constexpr int NT = 64;
    constexpr int CG = M / 4;
    constexpr int NG = 256 / CG;
    constexpr int NPT = NT / NG;
    constexpr int KC = 16;
    __shared__ float Ws[KC * M];
    __shared__ float Xs[NT * K];

    const float* X = (xid >= 0) ? getbuf(xid) : Xext;
    float* Y = getbuf(yid);
    uint2* Ohi = (uint2*)gs_hi(op);
    uint2* Olo = (uint2*)gs_lo(op);

    int tid = threadIdx.x;
    const int c = tid % CG;
    const int g = tid / CG;
    const float4* Ws4 = (const float4*)Ws;
    int ntiles = (nrows + NT - 1) / NT;

    for (int tile = blockIdx.x; tile < ntiles; tile += gridDim.x) {
        int row0 = tile * NT;
        __syncthreads();
        for (int i = tid; i < NT * K; i += 256) {
            int rr = i / K, kk = i % K;
            int r = row0 + rr;
            Xs[i] = (r < nrows) ? X[(long long)r * K + kk] : 0.f;
        }
        float4 acc[NPT];
#pragma unroll
        for (int r = 0; r < NPT; r++) acc[r] = make_float4(0.f, 0.f, 0.f, 0.f);

        for (int kc0 = 0; kc0 < K; kc0 += KC) {
            __syncthreads();
            for (int i = tid; i < KC * M; i += 256) Ws[i] = W[kc0 * M + i];
            __syncthreads();
#pragma unroll
            for (int k = 0; k < KC; k++) {
                float4 w = Ws4[k * CG + c];
#pragma unroll
                for (int r = 0; r < NPT; r++) {
                    float xv = Xs[(g * NPT + r) * K + kc0 + k];
                    acc[r].x = fmaf(xv, w.x, acc[r].x);
                    acc[r].y = fmaf(xv, w.y, acc[r].y);
                    acc[r].z = fmaf(xv, w.z, acc[r].z);
                    acc[r].w = fmaf(xv, w.w, acc[r].w);
                }
            }
        }
        float4 bv = make_float4(0.f, 0.f, 0.f, 0.f);
        if (BMODE >= 1) bv = ((const float4*)bias)[c];
#pragma unroll
        for (int r = 0; r < NPT; r++) {
            int row = row0 + g * NPT + r;
            if (row < nrows) {
                float4 v;
                v.x = acc[r].x + bv.x;
                v.y = acc[r].y + bv.y;
                v.z = acc[r].z + bv.z;
                v.w = acc[r].w + bv.w;
                if (RELU) {
                    v.x = fmaxf(v.x, 0.f);
                    v.y = fmaxf(v.y, 0.f);
                    v.z = fmaxf(v.z, 0.f);
                    v.w = fmaxf(v.w, 0.f);
                }
                if (OSPLIT) {
                    uint2 hi, lo;
                    split4_u2(v, hi, lo);
                    Ohi[(long long)row * (M / 4) + c] = hi;
                    Olo[(long long)row * (M / 4) + c] = lo;
                } else {
                    ((float4*)Y)[(long long)row * CG + c] = v;
                }
            }
        }
    }
}

// ---------------- edge gather: split output into pair 0 ----------------
__global__ void k_gather(const float* W1p, const float* b1) {
    int lane = threadIdx.x & 31;
    int wid = (blockIdx.x * blockDim.x + threadIdx.x) >> 5;
    int nwarps = (gridDim.x * blockDim.x) >> 5;
    const float4* W4 = (const float4*)W1p;
    float4 w0 = W4[0 * 32 + lane];
    float4 w1 = W4[1 * 32 + lane];
    float4 w2 = W4[2 * 32 + lane];
    float4 w3 = W4[3 * 32 + lane];
    float4 bb = ((const float4*)b1)[lane];
    const float4* t4 = (const float4*)g_t;
    uint2* Ohi = (uint2*)g_s0h;
    uint2* Olo = (uint2*)g_s0l;
    for (int node = wid; node < NN; node += nwarps) {
        int s0 = g_rowptr[node];
        int s1 = g_rowptr[node + 1];
        float4 acc = make_float4(0.f, 0.f, 0.f, 0.f);
        for (int s = s0; s < s1; s++) {
            int src = g_srcs[s];
            float4 pf = g_ppf[s];
            float4 tv = t4[(long long)src * 32 + lane];
            float4 h;
            h.x = bb.x + tv.x;
            h.y = bb.y + tv.y;
            h.z = bb.z + tv.z;
            h.w = bb.w + tv.w;
            h.x = fmaf(pf.x, w0.x, h.x); h.y = fmaf(pf.x, w0.y, h.y); h.z = fmaf(pf.x, w0.z, h.z); h.w = fmaf(pf.x, w0.w, h.w);
            h.x = fmaf(pf.y, w1.x, h.x); h.y = fmaf(pf.y, w1.y, h.y); h.z = fmaf(pf.y, w1.z, h.z); h.w = fmaf(pf.y, w1.w, h.w);
            h.x = fmaf(pf.z, w2.x, h.x); h.y = fmaf(pf.z, w2.y, h.y); h.z = fmaf(pf.z, w2.z, h.z); h.w = fmaf(pf.z, w2.w, h.w);
            h.x = fmaf(pf.w, w3.x, h.x); h.y = fmaf(pf.w, w3.y, h.y); h.z = fmaf(pf.w, w3.z, h.z); h.w = fmaf(pf.w, w3.w, h.w);
            acc.x += fmaxf(h.x, 0.f);
            acc.y += fmaxf(h.y, 0.f);
            acc.z += fmaxf(h.z, 0.f);
            acc.w += fmaxf(h.w, 0.f);
        }
        uint2 hi, lo;
        split4_u2(acc, hi, lo);
        Ohi[(long long)node * 32 + lane] = hi;
        Olo[(long long)node * 32 + lane] = lo;
    }
}

// ---------------- per-graph reduction ----------------
__global__ void k_out(const void* batch) {
    int i = blockIdx.x * blockDim.x + threadIdx.x;
    if (i < NN * 16) {
        int n = i >> 4, j = i & 15;
        int b = load_idx(batch, n, g_is64);
        atomicAdd(&g_out[b * 16 + j], g_t[i]);
    }
}

__global__ void k_copy(float* out) {
    int i = blockIdx.x * blockDim.x + threadIdx.x;
    if (i < GG * 16) out[i] = g_out[i];
}

// ---------------- launch ----------------
extern "C" void kernel_launch(void* const* d_in, const int* in_sizes, int n_in,
                              void* d_out, int out_size) {
    const float* x     = (const float*)d_in[0];
    const float* pos   = (const float*)d_in[1];
    const void*  ei    = d_in[2];
    const void*  batch = d_in[3];
    const float* nW1 = (const float*)d_in[4];
    const float* nb1 = (const float*)d_in[5];
    const float* nW2 = (const float*)d_in[6];
    const float* nb2 = (const float*)d_in[7];
    const float* lW1 = (const float*)d_in[8];
    const float* lb1 = (const float*)d_in[9];
    const float* lW2 = (const float*)d_in[10];
    const float* lb2 = (const float*)d_in[11];
    const float* gW1 = (const float*)d_in[12];
    const float* gb1 = (const float*)d_in[13];
    const float* gW2 = (const float*)d_in[14];
    const float* gb2 = (const float*)d_in[15];
    const float* l1W = (const float*)d_in[16];
    const float* l1b = (const float*)d_in[17];
    const float* l2W = (const float*)d_in[18];
    const float* l2b = (const float*)d_in[19];
    float* out = (float*)d_out;

    cudaFuncSetAttribute(k_mmagemm<1, false, true, false>, cudaFuncAttributeMaxDynamicSharedMemorySize, SM_BYTES);
    cudaFuncSetAttribute(k_mmagemm<3, true, false, true>,  cudaFuncAttributeMaxDynamicSharedMemorySize, SM_BYTES);
    cudaFuncSetAttribute(k_mmagemm<1, true, true, true>,   cudaFuncAttributeMaxDynamicSharedMemorySize, SM_BYTES);
    cudaFuncSetAttribute(k_mmagemm<0, false, true, false>, cudaFuncAttributeMaxDynamicSharedMemorySize, SM_BYTES);

    const int GB = 296;
    const int GT = 148;

    k_detect<<<1, 1024>>>(ei);
    k_init<<<(NN + 255) / 256, 256>>>();
    k_hist<<<(EE + 255) / 256, 256>>>(ei);
    k_scan1<<<NB_SCAN, 1024>>>();
    k_scan2<<<1, 128>>>();
    k_fin<<<NB_SCAN, 1024>>>();
    k_scatter<<<(EE + 255) / 256, 256>>>(ei, pos);

    // q = relu(x@nW1 + nb1)             -> split pair 0
    k_gemm<16, 128, 1, true, true><<<GB, 256>>>(-1, x, nW1, nb1, 3, 0, NN);
    // g_F = nW2@W1h_0, g_c = nb2@W1h_0 ; t0 = q@g_F + g_c -> buf1 (fp32)
    k_combine<<<129, 128>>>(nW2, lW1 + 0 * 132 * 128, nb2);
    k_split<<<8, 256>>>(nullptr, 1);
    k_mmagemm<1, false, true, false><<<GT, 256, SM_BYTES>>>(0, nullptr, 1, 0, NN);

    for (int l = 0; l < LL; l++) {
        const float* W1p = lW1 + l * 132 * 128 + 128 * 128;
        // r = gather(t=buf1)                       -> split pair 0
        k_gather<<<1184, 256>>>(W1p, lb1 + l * 128);
        // g_F = lW2_l@gW1_l, g_c = lb2_l@gW1_l
        k_combine<<<129, 128>>>(lW2 + l * 128 * 128, gW1 + l * 128 * 128, lb2 + l * 128);
        k_split<<<8, 256>>>(nullptr, 1);
        // u = relu(r@g_F + gb1 + deg*g_c)          -> split pair 1
        k_mmagemm<3, true, false, true><<<GT, 256, SM_BYTES>>>(0, gb1 + l * 128, 3, 1, NN);
        // h = relu(u@gW2 + gb2)                    -> buf0 (fp32) + split pair 0
        k_split<<<8, 256>>>(gW2 + l * 128 * 128, 0);
        k_mmagemm<1, true, true, true><<<GT, 256, SM_BYTES>>>(1, gb2 + l * 128, 0, 0, NN);
        if (l + 1 < LL) {
            // t_{l+1} = h @ W1h_{l+1}              -> buf1 (fp32)
            k_split<<<8, 256>>>(lW1 + (l + 1) * 132 * 128, 0);
            k_mmagemm<0, false, true, false><<<GT, 256, SM_BYTES>>>(0, nullptr, 1, 0, NN);
        }
    }

    // head: buf0 -> buf3 -> buf1 -> out
    k_gemm<128, 64, 1, true, false><<<GB, 256>>>(0, nullptr, l1W, l1b, 3, 0, NN);
    k_gemm<64, 16, 1, false, false><<<GB, 256>>>(3, nullptr, l2W, l2b, 1, 0, NN);
    k_out<<<(NN * 16 + 255) / 256, 256>>>(batch);
    k_copy<<<(GG * 16 + 255) / 256, 256>>>(out);
}

// round 10
// speedup vs baseline: 1.0631x; 1.0631x over previous
#include <cuda_runtime.h>
#include <cuda_bf16.h>
#include <math.h>
#include <stdint.h>

#define NN 100000
#define EE 1600000
#define HH 128
#define GG 256
#define LL 3
#define NB_SCAN ((NN + 1023) / 1024)   // 98
#define NTILES ((NN + 127) / 128)      // 782

// padded k-major bf16 tile in smem: 128 rows x 136 halves (272 B row pitch)
#define RPITCH 272
#define TILE_U4 2176   // 128 * 17 uint4

// ---------------- scratch (device globals; no allocation) ----------------
__device__ __align__(16) float g_h[NN * HH];
__device__ __align__(16) float g_t[NN * HH];
__device__ __align__(16) float g_r[NN * HH];
__device__ __align__(16) float g_tmp[NN * HH];
__device__ __align__(16) float g_out[GG * 16];
__device__ __align__(16) float g_F[HH * HH];
__device__ __align__(16) float g_c[HH];
__device__ __align__(16) uint4 g_Bhi[TILE_U4];   // W^T bf16 hi (padded k-major)
__device__ __align__(16) uint4 g_Blo[TILE_U4];   // W^T bf16 lo
// pre-split activation buffers (row-major, 16 uint4 = 128 bf16 per row), 2 ping-pong pairs
__device__ __align__(16) uint4 g_s0h[NN * 16];
__device__ __align__(16) uint4 g_s0l[NN * 16];
__device__ __align__(16) uint4 g_s1h[NN * 16];
__device__ __align__(16) uint4 g_s1l[NN * 16];
__device__ int    g_deg[NN];
__device__ int    g_incl[NN];
__device__ int    g_rowptr[NN + 1];
__device__ int    g_cursor[NN];
__device__ int    g_srcs[EE];
__device__ float4 g_ppf[EE];
__device__ int    g_bsum[128];
__device__ int    g_is64;

__device__ __forceinline__ float* getbuf(int id) {
    switch (id) {
        case 0: return g_h;
        case 1: return g_t;
        case 2: return g_r;
        default: return g_tmp;
    }
}
__device__ __forceinline__ uint4* gs_hi(int id) { return id ? g_s1h : g_s0h; }
__device__ __forceinline__ uint4* gs_lo(int id) { return id ? g_s1l : g_s0l; }

__device__ __forceinline__ int load_idx(const void* p, long long i, int is64) {
    if (is64) return (int)((const long long*)p)[i];
    return ((const int*)p)[i];
}

// ================= mma.sync + cp.async helpers (baseline sm_80+ PTX) =================
__device__ __forceinline__ uint32_t smem_u32(const void* p) {
    uint32_t a;
    asm("{ .reg .u64 t; cvta.to.shared.u64 t, %1; cvt.u32.u64 %0, t; }" : "=r"(a) : "l"(p));
    return a;
}
__device__ __forceinline__ void ldm4(uint32_t* r, uint32_t addr) {
    asm volatile("ldmatrix.sync.aligned.m8n8.x4.shared.b16 {%0,%1,%2,%3}, [%4];"
        : "=r"(r[0]), "=r"(r[1]), "=r"(r[2]), "=r"(r[3]) : "r"(addr));
}
__device__ __forceinline__ void mma16816(float* d, const uint32_t* a, uint32_t b0, uint32_t b1) {
    asm volatile("mma.sync.aligned.m16n8k16.row.col.f32.bf16.bf16.f32 "
        "{%0,%1,%2,%3}, {%4,%5,%6,%7}, {%8,%9}, {%0,%1,%2,%3};"
        : "+f"(d[0]), "+f"(d[1]), "+f"(d[2]), "+f"(d[3])
        : "r"(a[0]), "r"(a[1]), "r"(a[2]), "r"(a[3]), "r"(b0), "r"(b1));
}
__device__ __forceinline__ void cpa16(uint32_t dst, const void* src, unsigned sz) {
    asm volatile("cp.async.cg.shared.global [%0], [%1], 16, %2;"
        :: "r"(dst), "l"(src), "r"(sz) : "memory");
}
#define CPA_COMMIT() asm volatile("cp.async.commit_group;" ::: "memory")
#define CPA_WAIT(n)  asm volatile("cp.async.wait_group %0;" :: "n"(n) : "memory")

// split helpers
__device__ __forceinline__ void split1(float v, unsigned& h, unsigned& l) {
    __nv_bfloat16 hb = __float2bfloat16(v);
    float rem = v - __bfloat162float(hb);
    __nv_bfloat16 lb = __float2bfloat16(rem);
    h = (unsigned)__bfloat16_as_ushort(hb);
    l = (unsigned)__bfloat16_as_ushort(lb);
}
__device__ __forceinline__ void split8(const float* v, uint4& hi, uint4& lo) {
    unsigned hs[8], ls[8];
#pragma unroll
    for (int j = 0; j < 8; j++) split1(v[j], hs[j], ls[j]);
    hi = make_uint4(hs[0] | (hs[1] << 16), hs[2] | (hs[3] << 16), hs[4] | (hs[5] << 16), hs[6] | (hs[7] << 16));
    lo = make_uint4(ls[0] | (ls[1] << 16), ls[2] | (ls[3] << 16), ls[4] | (ls[5] << 16), ls[6] | (ls[7] << 16));
}
__device__ __forceinline__ void split4_u2(const float4& v, uint2& hi, uint2& lo) {
    unsigned h0, h1, h2, h3, l0, l1, l2, l3;
    split1(v.x, h0, l0); split1(v.y, h1, l1); split1(v.z, h2, l2); split1(v.w, h3, l3);
    hi = make_uint2(h0 | (h1 << 16), h2 | (h3 << 16));
    lo = make_uint2(l0 | (l1 << 16), l2 | (l3 << 16));
}

// ---------------- dtype detection ----------------
__global__ void k_detect(const void* ei) {
    __shared__ int s_nz;
    if (threadIdx.x == 0) s_nz = 0;
    __syncthreads();
    const int* w = (const int*)ei;
    int v = w[2 * threadIdx.x + 1];
    int v2 = w[2 * (threadIdx.x + 1024) + 1];
    if ((v | v2) != 0) atomicOr(&s_nz, 1);
    __syncthreads();
    if (threadIdx.x == 0) g_is64 = s_nz ? 0 : 1;
}

__global__ void k_init() {
    int i = blockIdx.x * blockDim.x + threadIdx.x;
    if (i < GG * 16) g_out[i] = 0.f;
    if (i < NN) g_deg[i] = 0;
}

__global__ void k_hist(const void* ei) {
    int e = blockIdx.x * blockDim.x + threadIdx.x;
    if (e < EE) {
        int d = load_idx(ei, (long long)EE + e, g_is64);
        atomicAdd(&g_deg[d], 1);
    }
}

__global__ void k_scan1() {
    __shared__ int s[1024];
    int tid = threadIdx.x;
    int i = blockIdx.x * 1024 + tid;
    int v = (i < NN) ? g_deg[i] : 0;
    s[tid] = v;
    __syncthreads();
    for (int off = 1; off < 1024; off <<= 1) {
        int a = (tid >= off) ? s[tid - off] : 0;
        __syncthreads();
        s[tid] += a;
        __syncthreads();
    }
    if (i < NN) g_incl[i] = s[tid];
    if (tid == 1023) g_bsum[blockIdx.x] = s[1023];
}

__global__ void k_scan2() {
    __shared__ int s[128];
    int tid = threadIdx.x;
    s[tid] = (tid < NB_SCAN) ? g_bsum[tid] : 0;
    __syncthreads();
    for (int off = 1; off < 128; off <<= 1) {
        int a = (tid >= off) ? s[tid - off] : 0;
        __syncthreads();
        s[tid] += a;
        __syncthreads();
    }
    if (tid < NB_SCAN) g_bsum[tid] = s[tid];
}

__global__ void k_fin() {
    int tid = threadIdx.x;
    int i = blockIdx.x * 1024 + tid;
    if (i < NN) {
        int off = blockIdx.x ? g_bsum[blockIdx.x - 1] : 0;
        int excl = g_incl[i] - g_deg[i] + off;
        g_rowptr[i] = excl;
        g_cursor[i] = excl;
    }
    if (i == 0) g_rowptr[NN] = EE;
}

__device__ __forceinline__ float dot3(float ax, float ay, float az, float bx, float by, float bz) {
    return ax * bx + ay * by + az * bz;
}
__device__ __forceinline__ float crossnorm(float ax, float ay, float az, float bx, float by, float bz) {
    float cx = ay * bz - az * by;
    float cy = az * bx - ax * bz;
    float cz = ax * by - ay * bx;
    return sqrtf(cx * cx + cy * cy + cz * cz);
}

__global__ void k_scatter(const void* ei, const float* pos) {
    int e = blockIdx.x * blockDim.x + threadIdx.x;
    if (e >= EE) return;
    int is64 = g_is64;
    int s = load_idx(ei, e, is64);
    int d = load_idx(ei, (long long)EE + e, is64);
    float pix = pos[3 * d], piy = pos[3 * d + 1], piz = pos[3 * d + 2];
    float pjx = pos[3 * s], pjy = pos[3 * s + 1], pjz = pos[3 * s + 2];
    float nin = sqrtf(pix * pix + piy * piy + piz * piz) + 1e-12f;
    float njn = sqrtf(pjx * pjx + pjy * pjy + pjz * pjz) + 1e-12f;
    float nix = pix / nin, niy = piy / nin, niz = piz / nin;
    float njx = pjx / njn, njy = pjy / njn, njz = pjz / njn;
    float dx = pjx - pix, dy = pjy - piy, dz = pjz - piz;
    float f0 = sqrtf(dx * dx + dy * dy + dz * dz);
    float f1 = atan2f(crossnorm(nix, niy, niz, dx, dy, dz), dot3(nix, niy, niz, dx, dy, dz));
    float f2 = atan2f(crossnorm(njx, njy, njz, dx, dy, dz), dot3(njx, njy, njz, dx, dy, dz));
    float f3 = atan2f(crossnorm(nix, niy, niz, njx, njy, njz), dot3(nix, niy, niz, njx, njy, njz));
    int slot = atomicAdd(&g_cursor[d], 1);
    g_srcs[slot] = s;
    g_ppf[slot] = make_float4(f0, f1, f2, f3);
}

// ---------------- g_F = A@B (128x128), g_c = v@B ----------------
__global__ void k_combine(const float* A, const float* B, const float* v) {
    int col = threadIdx.x;
    int row = blockIdx.x;
    if (row < 128) {
        float s = 0.f;
        for (int k = 0; k < 128; k++) s = fmaf(A[row * 128 + k], B[k * 128 + col], s);
        g_F[row * 128 + col] = s;
    } else {
        float s = 0.f;
        for (int k = 0; k < 128; k++) s = fmaf(v[k], B[k * 128 + col], s);
        g_c[col] = s;
    }
}

// ---------------- weight split: W[k][n] (or g_F) -> g_Bhi/g_Blo (padded k-major) ----------------
__global__ void k_split(const float* W, int wsel) {
    const float* src = wsel ? g_F : W;
    int i = blockIdx.x * blockDim.x + threadIdx.x;
    if (i >= 2048) return;
    int n = i >> 4, kg = i & 15;
    float v[8];
#pragma unroll
    for (int j = 0; j < 8; j++) v[j] = src[(kg * 8 + j) * 128 + n];
    uint4 hi, lo;
    split8(v, hi, lo);
    g_Bhi[n * 17 + kg] = hi;
    g_Blo[n * 17 + kg] = lo;
}

// ---------------- pipelined HMMA GEMM ----------------
// Input: pre-split bf16 pair ip. Outputs: fp32 buf yid (if OF32) and/or split pair op (if OSPLIT).
// BMODE: 0 none, 1 bias (bias==nullptr -> g_c), 3 bias + deg*g_c
#define SM_BHI 0
#define SM_BLO 34816
#define SM_A0H 69632
#define SM_A0L 104448
#define SM_A1H 139264
#define SM_A1L 174080
#define SM_BYTES 208896

__device__ __forceinline__ void issue_copy(uint32_t aH, uint32_t aL,
                                           const uint4* Xhi, const uint4* Xlo,
                                           int row0, int nrows, int tid) {
#pragma unroll
    for (int i = tid; i < 2048; i += 256) {
        int row = i >> 4, grp = i & 15;
        int r = row0 + row;
        unsigned sz = (r < nrows) ? 16u : 0u;
        long long rc = (r < nrows) ? r : 0;
        uint32_t off = (uint32_t)(row * RPITCH + grp * 16);
        cpa16(aH + off, &Xhi[rc * 16 + grp], sz);
        cpa16(aL + off, &Xlo[rc * 16 + grp], sz);
    }
}

template <int BMODE, bool RELU, bool OF32, bool OSPLIT>
__global__ void __launch_bounds__(256, 1) k_mmagemm(int ip, const float* bias, int yid, int op, int nrows) {
    extern __shared__ char sm[];
    const uint4* Xhi = gs_hi(ip);
    const uint4* Xlo = gs_lo(ip);
    float* Y = getbuf(yid);
    ushort2* Ohi = (ushort2*)gs_hi(op);
    ushort2* Olo = (ushort2*)gs_lo(op);

    int tid = threadIdx.x;
    int wid = tid >> 5;
    int lane = tid & 31;

    // persistent weights into smem
    uint4* bhi_s = (uint4*)(sm + SM_BHI);
    uint4* blo_s = (uint4*)(sm + SM_BLO);
    for (int i = tid; i < TILE_U4; i += 256) {
        bhi_s[i] = g_Bhi[i];
        blo_s[i] = g_Blo[i];
    }

    const int mrow0 = (wid & 3) * 32;
    const int ncol0 = (wid >> 2) * 64;
    const int lrow = lane & 15;
    const int lkof = ((lane >> 4) << 3) * 2;

    uint32_t a0h = smem_u32(sm + SM_A0H), a0l = smem_u32(sm + SM_A0L);
    uint32_t a1h = smem_u32(sm + SM_A1H), a1l = smem_u32(sm + SM_A1L);
    uint32_t b_base_hi = smem_u32(sm + SM_BHI);
    uint32_t b_base_lo = smem_u32(sm + SM_BLO);

    // prologue: prefetch first tile into stage 0
    int tile0 = blockIdx.x;
    if (tile0 < NTILES) {
        issue_copy(a0h, a0l, Xhi, Xlo, tile0 * 128, nrows, tid);
        CPA_COMMIT();
    }

    int it = 0;
    for (int tile = tile0; tile < NTILES; tile += gridDim.x, it++) {
        int par = it & 1;
        uint32_t aH = par ? a1h : a0h;
        uint32_t aL = par ? a1l : a0l;
        int nxt = tile + gridDim.x;
        if (nxt < NTILES) {
            issue_copy(par ? a0h : a1h, par ? a0l : a1l, Xhi, Xlo, nxt * 128, nrows, tid);
            CPA_COMMIT();
            CPA_WAIT(1);   // current tile's copy done; next stays in flight
        } else {
            CPA_WAIT(0);
        }
        __syncthreads();

        int row0 = tile * 128;
        float d[2][8][4];
#pragma unroll
        for (int mt = 0; mt < 2; mt++)
#pragma unroll
            for (int nt = 0; nt < 8; nt++)
#pragma unroll
                for (int j = 0; j < 4; j++) d[mt][nt][j] = 0.f;

#pragma unroll
        for (int kk = 0; kk < 8; kk++) {
            int kb = kk * 32 + lkof;
            uint32_t ah[2][4], al[2][4];
#pragma unroll
            for (int mt = 0; mt < 2; mt++) {
                uint32_t off = (mrow0 + mt * 16 + lrow) * RPITCH + kb;
                ldm4(ah[mt], aH + off);
                ldm4(al[mt], aL + off);
            }
            uint32_t bh[4][4], bl[4][4];
#pragma unroll
            for (int np = 0; np < 4; np++) {
                uint32_t off = (ncol0 + np * 16 + lrow) * RPITCH + kb;
                ldm4(bh[np], b_base_hi + off);
                ldm4(bl[np], b_base_lo + off);
            }
#pragma unroll
            for (int mt = 0; mt < 2; mt++) {
#pragma unroll
                for (int np = 0; np < 4; np++) {
                    mma16816(d[mt][np * 2],     ah[mt], bh[np][0], bh[np][2]);
                    mma16816(d[mt][np * 2],     ah[mt], bl[np][0], bl[np][2]);
                    mma16816(d[mt][np * 2],     al[mt], bh[np][0], bh[np][2]);
                    mma16816(d[mt][np * 2 + 1], ah[mt], bh[np][1], bh[np][3]);
                    mma16816(d[mt][np * 2 + 1], ah[mt], bl[np][1], bl[np][3]);
                    mma16816(d[mt][np * 2 + 1], al[mt], bh[np][1], bh[np][3]);
                }
            }
        }

        int rbase = row0 + mrow0 + (lane >> 2);
        int cbase = ncol0 + 2 * (lane & 3);
#pragma unroll
        for (int mt = 0; mt < 2; mt++) {
            int r0 = rbase + mt * 16;
            int r1 = r0 + 8;
            float sc0 = 0.f, sc1 = 0.f;
            if (BMODE == 3) {
                if (r0 < nrows) sc0 = (float)g_deg[r0];
                if (r1 < nrows) sc1 = (float)g_deg[r1];
            }
#pragma unroll
            for (int nt = 0; nt < 8; nt++) {
                int c = cbase + nt * 8;
                float b0 = 0.f, b1 = 0.f, c0 = 0.f, c1 = 0.f;
                if (BMODE >= 1) {
                    const float* bp = (bias != nullptr) ? bias : g_c;
                    b0 = bp[c]; b1 = bp[c + 1];
                }
                if (BMODE == 3) { c0 = g_c[c]; c1 = g_c[c + 1]; }
                if (r0 < nrows) {
                    float v0 = d[mt][nt][0] + b0 + sc0 * c0;
                    float v1 = d[mt][nt][1] + b1 + sc0 * c1;
                    if (RELU) { v0 = fmaxf(v0, 0.f); v1 = fmaxf(v1, 0.f); }
                    if (OF32) *(float2*)&Y[(long long)r0 * 128 + c] = make_float2(v0, v1);
                    if (OSPLIT) {
                        unsigned h0, h1, l0, l1;
                        split1(v0, h0, l0); split1(v1, h1, l1);
                        long long idx = (long long)r0 * 64 + (c >> 1);
                        Ohi[idx] = make_ushort2((unsigned short)h0, (unsigned short)h1);
                        Olo[idx] = make_ushort2((unsigned short)l0, (unsigned short)l1);
                    }
                }
                if (r1 < nrows) {
                    float v2 = d[mt][nt][2] + b0 + sc1 * c0;
                    float v3 = d[mt][nt][3] + b1 + sc1 * c1;
                    if (RELU) { v2 = fmaxf(v2, 0.f); v3 = fmaxf(v3, 0.f); }
                    if (OF32) *(float2*)&Y[(long long)r1 * 128 + c] = make_float2(v2, v3);
                    if (OSPLIT) {
                        unsigned h2, h3, l2, l3;
                        split1(v2, h2, l2); split1(v3, h3, l3);
                        long long idx = (long long)r1 * 64 + (c >> 1);
                        Ohi[idx] = make_ushort2((unsigned short)h2, (unsigned short)h3);
                        Olo[idx] = make_ushort2((unsigned short)l2, (unsigned short)l3);
                    }
                }
            }
        }
        __syncthreads();
    }
}

// ---------------- small GEMM (K=16 node in + heads); optional split output ----------------
template <int K, int M, int BMODE, bool RELU, bool OSPLIT>
__global__ void k_gemm(int xid, const float* Xext,
                       const float* W, const float* bias,
                       int yid, int op, int nrows) {
    constexpr int NT = 64;
    constexpr int CG = M / 4;
    constexpr int NG = 256 / CG;
    constexpr int NPT = NT / NG;
    constexpr int KC = 16;
    __shared__ float Ws[KC * M];
    __shared__ float Xs[NT * K];

    const float* X = (xid >= 0) ? getbuf(xid) : Xext;
    float* Y = getbuf(yid);
    uint2* Ohi = (uint2*)gs_hi(op);
    uint2* Olo = (uint2*)gs_lo(op);

    int tid = threadIdx.x;
    const int c = tid % CG;
    const int g = tid / CG;
    const float4* Ws4 = (const float4*)Ws;
    int ntiles = (nrows + NT - 1) / NT;

    for (int tile = blockIdx.x; tile < ntiles; tile += gridDim.x) {
        int row0 = tile * NT;
        __syncthreads();
        for (int i = tid; i < NT * K; i += 256) {
            int rr = i / K, kk = i % K;
            int r = row0 + rr;
            Xs[i] = (r < nrows) ? X[(long long)r * K + kk] : 0.f;
        }
        float4 acc[NPT];
#pragma unroll
        for (int r = 0; r < NPT; r++) acc[r] = make_float4(0.f, 0.f, 0.f, 0.f);

        for (int kc0 = 0; kc0 < K; kc0 += KC) {
            __syncthreads();
            for (int i = tid; i < KC * M; i += 256) Ws[i] = W[kc0 * M + i];
            __syncthreads();
#pragma unroll
            for (int k = 0; k < KC; k++) {
                float4 w = Ws4[k * CG + c];
#pragma unroll
                for (int r = 0; r < NPT; r++) {
                    float xv = Xs[(g * NPT + r) * K + kc0 + k];
                    acc[r].x = fmaf(xv, w.x, acc[r].x);
                    acc[r].y = fmaf(xv, w.y, acc[r].y);
                    acc[r].z = fmaf(xv, w.z, acc[r].z);
                    acc[r].w = fmaf(xv, w.w, acc[r].w);
                }
            }
        }
        float4 bv = make_float4(0.f, 0.f, 0.f, 0.f);
        if (BMODE >= 1) bv = ((const float4*)bias)[c];
#pragma unroll
        for (int r = 0; r < NPT; r++) {
            int row = row0 + g * NPT + r;
            if (row < nrows) {
                float4 v;
                v.x = acc[r].x + bv.x;
                v.y = acc[r].y + bv.y;
                v.z = acc[r].z + bv.z;
                v.w = acc[r].w + bv.w;
                if (RELU) {
                    v.x = fmaxf(v.x, 0.f);
                    v.y = fmaxf(v.y, 0.f);
                    v.z = fmaxf(v.z, 0.f);
                    v.w = fmaxf(v.w, 0.f);
                }
                if (OSPLIT) {
                    uint2 hi, lo;
                    split4_u2(v, hi, lo);
                    Ohi[(long long)row * (M / 4) + c] = hi;
                    Olo[(long long)row * (M / 4) + c] = lo;
                } else {
                    ((float4*)Y)[(long long)row * CG + c] = v;
                }
            }
        }
    }
}

// ---------------- edge gather: split output into pair 0 ----------------
__global__ void k_gather(const float* W1p, const float* b1) {
    int lane = threadIdx.x & 31;
    int wid = (blockIdx.x * blockDim.x + threadIdx.x) >> 5;
    int nwarps = (gridDim.x * blockDim.x) >> 5;
    const float4* W4 = (const float4*)W1p;
    float4 w0 = W4[0 * 32 + lane];
    float4 w1 = W4[1 * 32 + lane];
    float4 w2 = W4[2 * 32 + lane];
    float4 w3 = W4[3 * 32 + lane];
    float4 bb = ((const float4*)b1)[lane];
    const float4* t4 = (const float4*)g_t;
    uint2* Ohi = (uint2*)g_s0h;
    uint2* Olo = (uint2*)g_s0l;
    for (int node = wid; node < NN; node += nwarps) {
        int s0 = g_rowptr[node];
        int s1 = g_rowptr[node + 1];
        float4 acc = make_float4(0.f, 0.f, 0.f, 0.f);
        for (int s = s0; s < s1; s++) {
            int src = g_srcs[s];
            float4 pf = g_ppf[s];
            float4 tv = t4[(long long)src * 32 + lane];
            float4 h;
            h.x = bb.x + tv.x;
            h.y = bb.y + tv.y;
            h.z = bb.z + tv.z;
            h.w = bb.w + tv.w;
            h.x = fmaf(pf.x, w0.x, h.x); h.y = fmaf(pf.x, w0.y, h.y); h.z = fmaf(pf.x, w0.z, h.z); h.w = fmaf(pf.x, w0.w, h.w);
            h.x = fmaf(pf.y, w1.x, h.x); h.y = fmaf(pf.y, w1.y, h.y); h.z = fmaf(pf.y, w1.z, h.z); h.w = fmaf(pf.y, w1.w, h.w);
            h.x = fmaf(pf.z, w2.x, h.x); h.y = fmaf(pf.z, w2.y, h.y); h.z = fmaf(pf.z, w2.z, h.z); h.w = fmaf(pf.z, w2.w, h.w);
            h.x = fmaf(pf.w, w3.x, h.x); h.y = fmaf(pf.w, w3.y, h.y); h.z = fmaf(pf.w, w3.z, h.z); h.w = fmaf(pf.w, w3.w, h.w);
            acc.x += fmaxf(h.x, 0.f);
            acc.y += fmaxf(h.y, 0.f);
            acc.z += fmaxf(h.z, 0.f);
            acc.w += fmaxf(h.w, 0.f);
        }
        uint2 hi, lo;
        split4_u2(acc, hi, lo);
        Ohi[(long long)node * 32 + lane] = hi;
        Olo[(long long)node * 32 + lane] = lo;
    }
}

// ---------------- per-graph reduction ----------------
__global__ void k_out(const void* batch) {
    int i = blockIdx.x * blockDim.x + threadIdx.x;
    if (i < NN * 16) {
        int n = i >> 4, j = i & 15;
        int b = load_idx(batch, n, g_is64);
        atomicAdd(&g_out[b * 16 + j], g_t[i]);
    }
}

__global__ void k_copy(float* out) {
    int i = blockIdx.x * blockDim.x + threadIdx.x;
    if (i < GG * 16) out[i] = g_out[i];
}

// ---------------- launch ----------------
extern "C" void kernel_launch(void* const* d_in, const int* in_sizes, int n_in,
                              void* d_out, int out_size) {
    const float* x     = (const float*)d_in[0];
    const float* pos   = (const float*)d_in[1];
    const void*  ei    = d_in[2];
    const void*  batch = d_in[3];
    const float* nW1 = (const float*)d_in[4];
    const float* nb1 = (const float*)d_in[5];
    const float* nW2 = (const float*)d_in[6];
    const float* nb2 = (const float*)d_in[7];
    const float* lW1 = (const float*)d_in[8];
    const float* lb1 = (const float*)d_in[9];
    const float* lW2 = (const float*)d_in[10];
    const float* lb2 = (const float*)d_in[11];
    const float* gW1 = (const float*)d_in[12];
    const float* gb1 = (const float*)d_in[13];
    const float* gW2 = (const float*)d_in[14];
    const float* gb2 = (const float*)d_in[15];
    const float* l1W = (const float*)d_in[16];
    const float* l1b = (const float*)d_in[17];
    const float* l2W = (const float*)d_in[18];
    const float* l2b = (const float*)d_in[19];
    float* out = (float*)d_out;

    cudaFuncSetAttribute(k_mmagemm<1, false, true, false>, cudaFuncAttributeMaxDynamicSharedMemorySize, SM_BYTES);
    cudaFuncSetAttribute(k_mmagemm<3, true, false, true>,  cudaFuncAttributeMaxDynamicSharedMemorySize, SM_BYTES);
    cudaFuncSetAttribute(k_mmagemm<1, true, false, true>,  cudaFuncAttributeMaxDynamicSharedMemorySize, SM_BYTES);
    cudaFuncSetAttribute(k_mmagemm<1, true, true, false>,  cudaFuncAttributeMaxDynamicSharedMemorySize, SM_BYTES);
    cudaFuncSetAttribute(k_mmagemm<0, false, true, false>, cudaFuncAttributeMaxDynamicSharedMemorySize, SM_BYTES);

    const int GB = 296;
    const int GT = 148;

    k_detect<<<1, 1024>>>(ei);
    k_init<<<(NN + 255) / 256, 256>>>();
    k_hist<<<(EE + 255) / 256, 256>>>(ei);
    k_scan1<<<NB_SCAN, 1024>>>();
    k_scan2<<<1, 128>>>();
    k_fin<<<NB_SCAN, 1024>>>();
    k_scatter<<<(EE + 255) / 256, 256>>>(ei, pos);

    // q = relu(x@nW1 + nb1)             -> split pair 0
    k_gemm<16, 128, 1, true, true><<<GB, 256>>>(-1, x, nW1, nb1, 3, 0, NN);
    // g_F = nW2@W1h_0, g_c = nb2@W1h_0 ; t0 = q@g_F + g_c -> buf1 (fp32)
    k_combine<<<129, 128>>>(nW2, lW1 + 0 * 132 * 128, nb2);
    k_split<<<8, 256>>>(nullptr, 1);
    k_mmagemm<1, false, true, false><<<GT, 256, SM_BYTES>>>(0, nullptr, 1, 0, NN);

    for (int l = 0; l < LL; l++) {
        const float* W1p = lW1 + l * 132 * 128 + 128 * 128;
        // r = gather(t=buf1)                       -> split pair 0
        k_gather<<<1184, 256>>>(W1p, lb1 + l * 128);
        // g_F = lW2_l@gW1_l, g_c = lb2_l@gW1_l
        k_combine<<<129, 128>>>(lW2 + l * 128 * 128, gW1 + l * 128 * 128, lb2 + l * 128);
        k_split<<<8, 256>>>(nullptr, 1);
        // u = relu(r@g_F + gb1 + deg*g_c)          -> split pair 1
        k_mmagemm<3, true, false, true><<<GT, 256, SM_BYTES>>>(0, gb1 + l * 128, 3, 1, NN);
        // h = relu(u@gW2 + gb2)
        k_split<<<8, 256>>>(gW2 + l * 128 * 128, 0);
        if (l + 1 < LL) {
            // h -> split pair 0 only (feeds t_{l+1})
            k_mmagemm<1, true, false, true><<<GT, 256, SM_BYTES>>>(1, gb2 + l * 128, 0, 0, NN);
            // t_{l+1} = h @ W1h_{l+1}              -> buf1 (fp32)
            k_split<<<8, 256>>>(lW1 + (l + 1) * 132 * 128, 0);
            k_mmagemm<0, false, true, false><<<GT, 256, SM_BYTES>>>(0, nullptr, 1, 0, NN);
        } else {
            // final h -> buf0 (fp32) for the head
            k_mmagemm<1, true, true, false><<<GT, 256, SM_BYTES>>>(1, gb2 + l * 128, 0, 0, NN);
        }
    }

    // head: buf0 -> buf3 -> buf1 -> out
    k_gemm<128, 64, 1, true, false><<<GB, 256>>>(0, nullptr, l1W, l1b, 3, 0, NN);
    k_gemm<64, 16, 1, false, false><<<GB, 256>>>(3, nullptr, l2W, l2b, 1, 0, NN);
    k_out<<<(NN * 16 + 255) / 256, 256>>>(batch);
    k_copy<<<(GG * 16 + 255) / 256, 256>>>(out);
}

// round 11
// speedup vs baseline: 1.1645x; 1.0954x over previous
#include <cuda_runtime.h>
#include <cuda_bf16.h>
#include <math.h>
#include <stdint.h>

#define NN 100000
#define EE 1600000
#define HH 128
#define GG 256
#define LL 3
#define NB_SCAN ((NN + 1023) / 1024)   // 98
#define NTILES ((NN + 127) / 128)      // 782

// padded k-major bf16 tile in smem: 128 rows x 136 halves (272 B row pitch)
#define RPITCH 272
#define TILE_U4 2176   // 128 * 17 uint4
#define NSLOT 9

// ---------------- scratch (device globals; no allocation) ----------------
__device__ __align__(16) float g_h[NN * HH];
__device__ __align__(16) float g_t[NN * HH];
__device__ __align__(16) float g_r[NN * HH];
__device__ __align__(16) float g_tmp[NN * HH];
__device__ __align__(16) float g_out[GG * 16];
__device__ __align__(16) float g_F4[4][HH * HH];
__device__ __align__(16) float g_c4[4][HH];
__device__ __align__(16) uint4 g_Whi[NSLOT][TILE_U4];   // per-GEMM W^T bf16 hi
__device__ __align__(16) uint4 g_Wlo[NSLOT][TILE_U4];   // per-GEMM W^T bf16 lo
// pre-split activation buffers (row-major, 16 uint4 = 128 bf16 per row), 2 ping-pong pairs
__device__ __align__(16) uint4 g_s0h[NN * 16];
__device__ __align__(16) uint4 g_s0l[NN * 16];
__device__ __align__(16) uint4 g_s1h[NN * 16];
__device__ __align__(16) uint4 g_s1l[NN * 16];
__device__ int    g_deg[NN];
__device__ int    g_incl[NN];
__device__ int    g_rowptr[NN + 1];
__device__ int    g_cursor[NN];
__device__ int    g_srcs[EE];
__device__ float4 g_ppf[EE];
__device__ int    g_bsum[128];
__device__ int    g_is64;

__device__ __forceinline__ float* getbuf(int id) {
    switch (id) {
        case 0: return g_h;
        case 1: return g_t;
        case 2: return g_r;
        default: return g_tmp;
    }
}
__device__ __forceinline__ uint4* gs_hi(int id) { return id ? g_s1h : g_s0h; }
__device__ __forceinline__ uint4* gs_lo(int id) { return id ? g_s1l : g_s0l; }

__device__ __forceinline__ int load_idx(const void* p, long long i, int is64) {
    if (is64) return (int)((const long long*)p)[i];
    return ((const int*)p)[i];
}

// ================= mma.sync + cp.async helpers (baseline sm_80+ PTX) =================
__device__ __forceinline__ uint32_t smem_u32(const void* p) {
    uint32_t a;
    asm("{ .reg .u64 t; cvta.to.shared.u64 t, %1; cvt.u32.u64 %0, t; }" : "=r"(a) : "l"(p));
    return a;
}
__device__ __forceinline__ void ldm4(uint32_t* r, uint32_t addr) {
    asm volatile("ldmatrix.sync.aligned.m8n8.x4.shared.b16 {%0,%1,%2,%3}, [%4];"
        : "=r"(r[0]), "=r"(r[1]), "=r"(r[2]), "=r"(r[3]) : "r"(addr));
}
__device__ __forceinline__ void mma16816(float* d, const uint32_t* a, uint32_t b0, uint32_t b1) {
    asm volatile("mma.sync.aligned.m16n8k16.row.col.f32.bf16.bf16.f32 "
        "{%0,%1,%2,%3}, {%4,%5,%6,%7}, {%8,%9}, {%0,%1,%2,%3};"
        : "+f"(d[0]), "+f"(d[1]), "+f"(d[2]), "+f"(d[3])
        : "r"(a[0]), "r"(a[1]), "r"(a[2]), "r"(a[3]), "r"(b0), "r"(b1));
}
__device__ __forceinline__ void cpa16(uint32_t dst, const void* src, unsigned sz) {
    asm volatile("cp.async.cg.shared.global [%0], [%1], 16, %2;"
        :: "r"(dst), "l"(src), "r"(sz) : "memory");
}
#define CPA_COMMIT() asm volatile("cp.async.commit_group;" ::: "memory")
#define CPA_WAIT(n)  asm volatile("cp.async.wait_group %0;" :: "n"(n) : "memory")

// split helpers
__device__ __forceinline__ void split1(float v, unsigned& h, unsigned& l) {
    __nv_bfloat16 hb = __float2bfloat16(v);
    float rem = v - __bfloat162float(hb);
    __nv_bfloat16 lb = __float2bfloat16(rem);
    h = (unsigned)__bfloat16_as_ushort(hb);
    l = (unsigned)__bfloat16_as_ushort(lb);
}
__device__ __forceinline__ void split8(const float* v, uint4& hi, uint4& lo) {
    unsigned hs[8], ls[8];
#pragma unroll
    for (int j = 0; j < 8; j++) split1(v[j], hs[j], ls[j]);
    hi = make_uint4(hs[0] | (hs[1] << 16), hs[2] | (hs[3] << 16), hs[4] | (hs[5] << 16), hs[6] | (hs[7] << 16));
    lo = make_uint4(ls[0] | (ls[1] << 16), ls[2] | (ls[3] << 16), ls[4] | (ls[5] << 16), ls[6] | (ls[7] << 16));
}
__device__ __forceinline__ void split4_u2(const float4& v, uint2& hi, uint2& lo) {
    unsigned h0, h1, h2, h3, l0, l1, l2, l3;
    split1(v.x, h0, l0); split1(v.y, h1, l1); split1(v.z, h2, l2); split1(v.w, h3, l3);
    hi = make_uint2(h0 | (h1 << 16), h2 | (h3 << 16));
    lo = make_uint2(l0 | (l1 << 16), l2 | (l3 << 16));
}

// ---------------- dtype detection ----------------
__global__ void k_detect(const void* ei) {
    __shared__ int s_nz;
    if (threadIdx.x == 0) s_nz = 0;
    __syncthreads();
    const int* w = (const int*)ei;
    int v = w[2 * threadIdx.x + 1];
    int v2 = w[2 * (threadIdx.x + 1024) + 1];
    if ((v | v2) != 0) atomicOr(&s_nz, 1);
    __syncthreads();
    if (threadIdx.x == 0) g_is64 = s_nz ? 0 : 1;
}

__global__ void k_init() {
    int i = blockIdx.x * blockDim.x + threadIdx.x;
    if (i < GG * 16) g_out[i] = 0.f;
    if (i < NN) g_deg[i] = 0;
}

__global__ void k_hist(const void* ei) {
    int e = blockIdx.x * blockDim.x + threadIdx.x;
    if (e < EE) {
        int d = load_idx(ei, (long long)EE + e, g_is64);
        atomicAdd(&g_deg[d], 1);
    }
}

__global__ void k_scan1() {
    __shared__ int s[1024];
    int tid = threadIdx.x;
    int i = blockIdx.x * 1024 + tid;
    int v = (i < NN) ? g_deg[i] : 0;
    s[tid] = v;
    __syncthreads();
    for (int off = 1; off < 1024; off <<= 1) {
        int a = (tid >= off) ? s[tid - off] : 0;
        __syncthreads();
        s[tid] += a;
        __syncthreads();
    }
    if (i < NN) g_incl[i] = s[tid];
    if (tid == 1023) g_bsum[blockIdx.x] = s[1023];
}

__global__ void k_scan2() {
    __shared__ int s[128];
    int tid = threadIdx.x;
    s[tid] = (tid < NB_SCAN) ? g_bsum[tid] : 0;
    __syncthreads();
    for (int off = 1; off < 128; off <<= 1) {
        int a = (tid >= off) ? s[tid - off] : 0;
        __syncthreads();
        s[tid] += a;
        __syncthreads();
    }
    if (tid < NB_SCAN) g_bsum[tid] = s[tid];
}

__global__ void k_fin() {
    int tid = threadIdx.x;
    int i = blockIdx.x * 1024 + tid;
    if (i < NN) {
        int off = blockIdx.x ? g_bsum[blockIdx.x - 1] : 0;
        int excl = g_incl[i] - g_deg[i] + off;
        g_rowptr[i] = excl;
        g_cursor[i] = excl;
    }
    if (i == 0) g_rowptr[NN] = EE;
}

__device__ __forceinline__ float dot3(float ax, float ay, float az, float bx, float by, float bz) {
    return ax * bx + ay * by + az * bz;
}
__device__ __forceinline__ float crossnorm(float ax, float ay, float az, float bx, float by, float bz) {
    float cx = ay * bz - az * by;
    float cy = az * bx - ax * bz;
    float cz = ax * by - ay * bx;
    return sqrtf(cx * cx + cy * cy + cz * cz);
}

__global__ void k_scatter(const void* ei, const float* pos) {
    int e = blockIdx.x * blockDim.x + threadIdx.x;
    if (e >= EE) return;
    int is64 = g_is64;
    int s = load_idx(ei, e, is64);
    int d = load_idx(ei, (long long)EE + e, is64);
    float pix = pos[3 * d], piy = pos[3 * d + 1], piz = pos[3 * d + 2];
    float pjx = pos[3 * s], pjy = pos[3 * s + 1], pjz = pos[3 * s + 2];
    float nin = sqrtf(pix * pix + piy * piy + piz * piz) + 1e-12f;
    float njn = sqrtf(pjx * pjx + pjy * pjy + pjz * pjz) + 1e-12f;
    float nix = pix / nin, niy = piy / nin, niz = piz / nin;
    float njx = pjx / njn, njy = pjy / njn, njz = pjz / njn;
    float dx = pjx - pix, dy = pjy - piy, dz = pjz - piz;
    float f0 = sqrtf(dx * dx + dy * dy + dz * dz);
    float f1 = atan2f(crossnorm(nix, niy, niz, dx, dy, dz), dot3(nix, niy, niz, dx, dy, dz));
    float f2 = atan2f(crossnorm(njx, njy, njz, dx, dy, dz), dot3(njx, njy, njz, dx, dy, dz));
    float f3 = atan2f(crossnorm(nix, niy, niz, njx, njy, njz), dot3(nix, niy, niz, njx, njy, njz));
    int slot = atomicAdd(&g_cursor[d], 1);
    g_srcs[slot] = s;
    g_ppf[slot] = make_float4(f0, f1, f2, f3);
}

// ---------------- g_F4[fidx] = A@B (128x128), g_c4[fidx] = v@B ----------------
__global__ void k_combine(const float* A, const float* B, const float* v, int fidx) {
    int col = threadIdx.x;
    int row = blockIdx.x;
    if (row < 128) {
        float s = 0.f;
        for (int k = 0; k < 128; k++) s = fmaf(A[row * 128 + k], B[k * 128 + col], s);
        g_F4[fidx][row * 128 + col] = s;
    } else {
        float s = 0.f;
        for (int k = 0; k < 128; k++) s = fmaf(v[k], B[k * 128 + col], s);
        g_c4[fidx][col] = s;
    }
}

// ---------------- split all 9 weight slots (padded k-major W^T) ----------------
// slots: 0 = F0 (t0); 1..3 = F_{1+l} (u, layer l); 4..6 = gW2_l (h); 7..8 = W1h_{l+1} (t)
__global__ void k_split_all(const float* lW1, const float* gW2) {
    int g = blockIdx.x;          // 0..71
    int slot = g >> 3;
    int i = (g & 7) * 256 + threadIdx.x;   // 0..2047
    const float* src;
    if (slot <= 3) src = g_F4[slot];
    else if (slot <= 6) src = gW2 + (slot - 4) * 128 * 128;
    else src = lW1 + (slot - 6) * 132 * 128;
    int n = i >> 4, kg = i & 15;
    float v[8];
#pragma unroll
    for (int j = 0; j < 8; j++) v[j] = src[(kg * 8 + j) * 128 + n];
    uint4 hi, lo;
    split8(v, hi, lo);
    g_Whi[slot][n * 17 + kg] = hi;
    g_Wlo[slot][n * 17 + kg] = lo;
}

// ---------------- pipelined HMMA GEMM, 512 threads ----------------
// Input: pre-split bf16 pair ip + weight slot. Outputs: fp32 buf yid (OF32) and/or split pair op (OSPLIT).
// BMODE: 0 none, 1 bias (bias==nullptr -> g_c4[cidx]), 3 bias + deg*g_c4[cidx]
#define SM_BHI 0
#define SM_BLO 34816
#define SM_A0H 69632
#define SM_A0L 104448
#define SM_A1H 139264
#define SM_A1L 174080
#define SM_BYTES 208896

__device__ __forceinline__ void issue_copy(uint32_t aH, uint32_t aL,
                                           const uint4* Xhi, const uint4* Xlo,
                                           int row0, int nrows, int tid) {
#pragma unroll
    for (int i = tid; i < 2048; i += 512) {
        int row = i >> 4, grp = i & 15;
        int r = row0 + row;
        unsigned sz = (r < nrows) ? 16u : 0u;
        long long rc = (r < nrows) ? r : 0;
        uint32_t off = (uint32_t)(row * RPITCH + grp * 16);
        cpa16(aH + off, &Xhi[rc * 16 + grp], sz);
        cpa16(aL + off, &Xlo[rc * 16 + grp], sz);
    }
}

template <int BMODE, bool RELU, bool OF32, bool OSPLIT>
__global__ void __launch_bounds__(512, 1) k_mmagemm(int ip, int wslot, int cidx,
                                                    const float* bias, int yid, int op, int nrows) {
    extern __shared__ char sm[];
    const uint4* Xhi = gs_hi(ip);
    const uint4* Xlo = gs_lo(ip);
    float* Y = getbuf(yid);
    ushort2* Ohi = (ushort2*)gs_hi(op);
    ushort2* Olo = (ushort2*)gs_lo(op);
    const float* cvec = g_c4[cidx];

    int tid = threadIdx.x;
    int wid = tid >> 5;
    int lane = tid & 31;

    // persistent weights into smem
    uint4* bhi_s = (uint4*)(sm + SM_BHI);
    uint4* blo_s = (uint4*)(sm + SM_BLO);
    for (int i = tid; i < TILE_U4; i += 512) {
        bhi_s[i] = g_Whi[wslot][i];
        blo_s[i] = g_Wlo[wslot][i];
    }

    const int mrow0 = (wid & 7) * 16;     // warp's 16 rows
    const int ncol0 = (wid >> 3) * 64;    // warp's 64 cols
    const int lrow = lane & 15;
    const int lkof = ((lane >> 4) << 3) * 2;

    uint32_t a0h = smem_u32(sm + SM_A0H), a0l = smem_u32(sm + SM_A0L);
    uint32_t a1h = smem_u32(sm + SM_A1H), a1l = smem_u32(sm + SM_A1L);
    uint32_t b_base_hi = smem_u32(sm + SM_BHI);
    uint32_t b_base_lo = smem_u32(sm + SM_BLO);

    int tile0 = blockIdx.x;
    if (tile0 < NTILES) {
        issue_copy(a0h, a0l, Xhi, Xlo, tile0 * 128, nrows, tid);
        CPA_COMMIT();
    }

    int it = 0;
    for (int tile = tile0; tile < NTILES; tile += gridDim.x, it++) {
        int par = it & 1;
        uint32_t aH = par ? a1h : a0h;
        uint32_t aL = par ? a1l : a0l;
        int nxt = tile + gridDim.x;
        if (nxt < NTILES) {
            issue_copy(par ? a0h : a1h, par ? a0l : a1l, Xhi, Xlo, nxt * 128, nrows, tid);
            CPA_COMMIT();
            CPA_WAIT(1);
        } else {
            CPA_WAIT(0);
        }
        __syncthreads();

        int row0 = tile * 128;
        float d[8][4];
#pragma unroll
        for (int nt = 0; nt < 8; nt++)
#pragma unroll
            for (int j = 0; j < 4; j++) d[nt][j] = 0.f;

#pragma unroll
        for (int kk = 0; kk < 8; kk++) {
            int kb = kk * 32 + lkof;
            uint32_t ah[4], al[4];
            {
                uint32_t off = (mrow0 + lrow) * RPITCH + kb;
                ldm4(ah, aH + off);
                ldm4(al, aL + off);
            }
            uint32_t bh[4][4], bl[4][4];
#pragma unroll
            for (int np = 0; np < 4; np++) {
                uint32_t off = (ncol0 + np * 16 + lrow) * RPITCH + kb;
                ldm4(bh[np], b_base_hi + off);
                ldm4(bl[np], b_base_lo + off);
            }
#pragma unroll
            for (int np = 0; np < 4; np++) {
                mma16816(d[np * 2],     ah, bh[np][0], bh[np][2]);
                mma16816(d[np * 2],     ah, bl[np][0], bl[np][2]);
                mma16816(d[np * 2],     al, bh[np][0], bh[np][2]);
                mma16816(d[np * 2 + 1], ah, bh[np][1], bh[np][3]);
                mma16816(d[np * 2 + 1], ah, bl[np][1], bl[np][3]);
                mma16816(d[np * 2 + 1], al, bh[np][1], bh[np][3]);
            }
        }

        int r0 = row0 + mrow0 + (lane >> 2);
        int r1 = r0 + 8;
        int cbase = ncol0 + 2 * (lane & 3);
        float sc0 = 0.f, sc1 = 0.f;
        if (BMODE == 3) {
            if (r0 < nrows) sc0 = (float)g_deg[r0];
            if (r1 < nrows) sc1 = (float)g_deg[r1];
        }
#pragma unroll
        for (int nt = 0; nt < 8; nt++) {
            int c = cbase + nt * 8;
            float b0 = 0.f, b1 = 0.f, c0 = 0.f, c1 = 0.f;
            if (BMODE >= 1) {
                const float* bp = (bias != nullptr) ? bias : cvec;
                b0 = bp[c]; b1 = bp[c + 1];
            }
            if (BMODE == 3) { c0 = cvec[c]; c1 = cvec[c + 1]; }
            if (r0 < nrows) {
                float v0 = d[nt][0] + b0 + sc0 * c0;
                float v1 = d[nt][1] + b1 + sc0 * c1;
                if (RELU) { v0 = fmaxf(v0, 0.f); v1 = fmaxf(v1, 0.f); }
                if (OF32) *(float2*)&Y[(long long)r0 * 128 + c] = make_float2(v0, v1);
                if (OSPLIT) {
                    unsigned h0, h1, l0, l1;
                    split1(v0, h0, l0); split1(v1, h1, l1);
                    long long idx = (long long)r0 * 64 + (c >> 1);
                    Ohi[idx] = make_ushort2((unsigned short)h0, (unsigned short)h1);
                    Olo[idx] = make_ushort2((unsigned short)l0, (unsigned short)l1);
                }
            }
            if (r1 < nrows) {
                float v2 = d[nt][2] + b0 + sc1 * c0;
                float v3 = d[nt][3] + b1 + sc1 * c1;
                if (RELU) { v2 = fmaxf(v2, 0.f); v3 = fmaxf(v3, 0.f); }
                if (OF32) *(float2*)&Y[(long long)r1 * 128 + c] = make_float2(v2, v3);
                if (OSPLIT) {
                    unsigned h2, h3, l2, l3;
                    split1(v2, h2, l2); split1(v3, h3, l3);
                    long long idx = (long long)r1 * 64 + (c >> 1);
                    Ohi[idx] = make_ushort2((unsigned short)h2, (unsigned short)h3);
                    Olo[idx] = make_ushort2((unsigned short)l2, (unsigned short)l3);
                }
            }
        }
        __syncthreads();
    }
}

// ---------------- small GEMM (K=16 node in + heads); optional split output ----------------
template <int K, int M, int BMODE, bool RELU, bool OSPLIT>
__global__ void k_gemm(int xid, const float* Xext,
                       const float* W, const float* bias,
                       int yid, int op, int nrows) {
    constexpr int NT = 64;
    constexpr int CG = M / 4;
    constexpr int NG = 256 / CG;
    constexpr int NPT = NT / NG;
    constexpr int KC = 16;
    __shared__ float Ws[KC * M];
    __shared__ float Xs[NT * K];

    const float* X = (xid >= 0) ? getbuf(xid) : Xext;
    float* Y = getbuf(yid);
    uint2* Ohi = (uint2*)gs_hi(op);
    uint2* Olo = (uint2*)gs_lo(op);

    int tid = threadIdx.x;
    const int c = tid % CG;
    const int g = tid / CG;
    const float4* Ws4 = (const float4*)Ws;
    int ntiles = (nrows + NT - 1) / NT;

    for (int tile = blockIdx.x; tile < ntiles; tile += gridDim.x) {
        int row0 = tile * NT;
        __syncthreads();
        for (int i = tid; i < NT * K; i += 256) {
            int rr = i / K, kk = i % K;
            int r = row0 + rr;
            Xs[i] = (r < nrows) ? X[(long long)r * K + kk] : 0.f;
        }
        float4 acc[NPT];
#pragma unroll
        for (int r = 0; r < NPT; r++) acc[r] = make_float4(0.f, 0.f, 0.f, 0.f);

        for (int kc0 = 0; kc0 < K; kc0 += KC) {
            __syncthreads();
            for (int i = tid; i < KC * M; i += 256) Ws[i] = W[kc0 * M + i];
            __syncthreads();
#pragma unroll
            for (int k = 0; k < KC; k++) {
                float4 w = Ws4[k * CG + c];
#pragma unroll
                for (int r = 0; r < NPT; r++) {
                    float xv = Xs[(g * NPT + r) * K + kc0 + k];
                    acc[r].x = fmaf(xv, w.x, acc[r].x);
                    acc[r].y = fmaf(xv, w.y, acc[r].y);
                    acc[r].z = fmaf(xv, w.z, acc[r].z);
                    acc[r].w = fmaf(xv, w.w, acc[r].w);
                }
            }
        }
        float4 bv = make_float4(0.f, 0.f, 0.f, 0.f);
        if (BMODE >= 1) bv = ((const float4*)bias)[c];
#pragma unroll
        for (int r = 0; r < NPT; r++) {
            int row = row0 + g * NPT + r;
            if (row < nrows) {
                float4 v;
                v.x = acc[r].x + bv.x;
                v.y = acc[r].y + bv.y;
                v.z = acc[r].z + bv.z;
                v.w = acc[r].w + bv.w;
                if (RELU) {
                    v.x = fmaxf(v.x, 0.f);
                    v.y = fmaxf(v.y, 0.f);
                    v.z = fmaxf(v.z, 0.f);
                    v.w = fmaxf(v.w, 0.f);
                }
                if (OSPLIT) {
                    uint2 hi, lo;
                    split4_u2(v, hi, lo);
                    Ohi[(long long)row * (M / 4) + c] = hi;
                    Olo[(long long)row * (M / 4) + c] = lo;
                } else {
                    ((float4*)Y)[(long long)row * CG + c] = v;
                }
            }
        }
    }
}

// ---------------- edge gather: split output into pair 0 ----------------
__global__ void k_gather(const float* W1p, const float* b1) {
    int lane = threadIdx.x & 31;
    int wid = (blockIdx.x * blockDim.x + threadIdx.x) >> 5;
    int nwarps = (gridDim.x * blockDim.x) >> 5;
    const float4* W4 = (const float4*)W1p;
    float4 w0 = W4[0 * 32 + lane];
    float4 w1 = W4[1 * 32 + lane];
    float4 w2 = W4[2 * 32 + lane];
    float4 w3 = W4[3 * 32 + lane];
    float4 bb = ((const float4*)b1)[lane];
    const float4* t4 = (const float4*)g_t;
    uint2* Ohi = (uint2*)g_s0h;
    uint2* Olo = (uint2*)g_s0l;
    for (int node = wid; node < NN; node += nwarps) {
        int s0 = g_rowptr[node];
        int s1 = g_rowptr[node + 1];
        float4 acc = make_float4(0.f, 0.f, 0.f, 0.f);
        for (int s = s0; s < s1; s++) {
            int src = g_srcs[s];
            float4 pf = g_ppf[s];
            float4 tv = t4[(long long)src * 32 + lane];
            float4 h;
            h.x = bb.x + tv.x;
            h.y = bb.y + tv.y;
            h.z = bb.z + tv.z;
            h.w = bb.w + tv.w;
            h.x = fmaf(pf.x, w0.x, h.x); h.y = fmaf(pf.x, w0.y, h.y); h.z = fmaf(pf.x, w0.z, h.z); h.w = fmaf(pf.x, w0.w, h.w);
            h.x = fmaf(pf.y, w1.x, h.x); h.y = fmaf(pf.y, w1.y, h.y); h.z = fmaf(pf.y, w1.z, h.z); h.w = fmaf(pf.y, w1.w, h.w);
            h.x = fmaf(pf.z, w2.x, h.x); h.y = fmaf(pf.z, w2.y, h.y); h.z = fmaf(pf.z, w2.z, h.z); h.w = fmaf(pf.z, w2.w, h.w);
            h.x = fmaf(pf.w, w3.x, h.x); h.y = fmaf(pf.w, w3.y, h.y); h.z = fmaf(pf.w, w3.z, h.z); h.w = fmaf(pf.w, w3.w, h.w);
            acc.x += fmaxf(h.x, 0.f);
            acc.y += fmaxf(h.y, 0.f);
            acc.z += fmaxf(h.z, 0.f);
            acc.w += fmaxf(h.w, 0.f);
        }
        uint2 hi, lo;
        split4_u2(acc, hi, lo);
        Ohi[(long long)node * 32 + lane] = hi;
        Olo[(long long)node * 32 + lane] = lo;
    }
}

// ---------------- per-graph reduction ----------------
__global__ void k_out(const void* batch) {
    int i = blockIdx.x * blockDim.x + threadIdx.x;
    if (i < NN * 16) {
        int n = i >> 4, j = i & 15;
        int b = load_idx(batch, n, g_is64);
        atomicAdd(&g_out[b * 16 + j], g_t[i]);
    }
}

__global__ void k_copy(float* out) {
    int i = blockIdx.x * blockDim.x + threadIdx.x;
    if (i < GG * 16) out[i] = g_out[i];
}

// ---------------- launch ----------------
extern "C" void kernel_launch(void* const* d_in, const int* in_sizes, int n_in,
                              void* d_out, int out_size) {
    const float* x     = (const float*)d_in[0];
    const float* pos   = (const float*)d_in[1];
    const void*  ei    = d_in[2];
    const void*  batch = d_in[3];
    const float* nW1 = (const float*)d_in[4];
    const float* nb1 = (const float*)d_in[5];
    const float* nW2 = (const float*)d_in[6];
    const float* nb2 = (const float*)d_in[7];
    const float* lW1 = (const float*)d_in[8];
    const float* lb1 = (const float*)d_in[9];
    const float* lW2 = (const float*)d_in[10];
    const float* lb2 = (const float*)d_in[11];
    const float* gW1 = (const float*)d_in[12];
    const float* gb1 = (const float*)d_in[13];
    const float* gW2 = (const float*)d_in[14];
    const float* gb2 = (const float*)d_in[15];
    const float* l1W = (const float*)d_in[16];
    const float* l1b = (const float*)d_in[17];
    const float* l2W = (const float*)d_in[18];
    const float* l2b = (const float*)d_in[19];
    float* out = (float*)d_out;

    cudaFuncSetAttribute(k_mmagemm<1, false, true, false>, cudaFuncAttributeMaxDynamicSharedMemorySize, SM_BYTES);
    cudaFuncSetAttribute(k_mmagemm<3, true, false, true>,  cudaFuncAttributeMaxDynamicSharedMemorySize, SM_BYTES);
    cudaFuncSetAttribute(k_mmagemm<1, true, false, true>,  cudaFuncAttributeMaxDynamicSharedMemorySize, SM_BYTES);
    cudaFuncSetAttribute(k_mmagemm<1, true, true, false>,  cudaFuncAttributeMaxDynamicSharedMemorySize, SM_BYTES);
    cudaFuncSetAttribute(k_mmagemm<0, false, true, false>, cudaFuncAttributeMaxDynamicSharedMemorySize, SM_BYTES);

    const int GB = 296;
    const int GT = 148;

    k_detect<<<1, 1024>>>(ei);
    k_init<<<(NN + 255) / 256, 256>>>();
    k_hist<<<(EE + 255) / 256, 256>>>(ei);
    k_scan1<<<NB_SCAN, 1024>>>();
    k_scan2<<<1, 128>>>();
    k_fin<<<NB_SCAN, 1024>>>();
    k_scatter<<<(EE + 255) / 256, 256>>>(ei, pos);

    // ---- weight prep, all up front ----
    k_combine<<<129, 128>>>(nW2, lW1 + 0 * 132 * 128, nb2, 0);
    for (int l = 0; l < LL; l++)
        k_combine<<<129, 128>>>(lW2 + l * 128 * 128, gW1 + l * 128 * 128, lb2 + l * 128, 1 + l);
    k_split_all<<<NSLOT * 8, 256>>>(lW1, gW2);

    // ---- main chain ----
    // q = relu(x@nW1 + nb1) -> split pair 0
    k_gemm<16, 128, 1, true, true><<<GB, 256>>>(-1, x, nW1, nb1, 3, 0, NN);
    // t0 = q@F0 + c0 -> buf1 (fp32)
    k_mmagemm<1, false, true, false><<<GT, 512, SM_BYTES>>>(0, 0, 0, nullptr, 1, 0, NN);

    for (int l = 0; l < LL; l++) {
        const float* W1p = lW1 + l * 132 * 128 + 128 * 128;
        // r = gather(t=buf1) -> split pair 0
        k_gather<<<1184, 256>>>(W1p, lb1 + l * 128);
        // u = relu(r@F_{1+l} + gb1 + deg*c_{1+l}) -> split pair 1
        k_mmagemm<3, true, false, true><<<GT, 512, SM_BYTES>>>(0, 1 + l, 1 + l, gb1 + l * 128, 3, 1, NN);
        if (l + 1 < LL) {
            // h = relu(u@gW2 + gb2) -> split pair 0
            k_mmagemm<1, true, false, true><<<GT, 512, SM_BYTES>>>(1, 4 + l, 0, gb2 + l * 128, 0, 0, NN);
            // t_{l+1} = h@W1h_{l+1} -> buf1 (fp32)
            k_mmagemm<0, false, true, false><<<GT, 512, SM_BYTES>>>(0, 7 + l, 0, nullptr, 1, 0, NN);
        } else {
            // final h -> buf0 (fp32) for the head
            k_mmagemm<1, true, true, false><<<GT, 512, SM_BYTES>>>(1, 6, 0, gb2 + l * 128, 0, 0, NN);
        }
    }

    // head: buf0 -> buf3 -> buf1 -> out
    k_gemm<128, 64, 1, true, false><<<GB, 256>>>(0, nullptr, l1W, l1b, 3, 0, NN);
    k_gemm<64, 16, 1, false, false><<<GB, 256>>>(3, nullptr, l2W, l2b, 1, 0, NN);
    k_out<<<(NN * 16 + 255) / 256, 256>>>(batch);
    k_copy<<<(GG * 16 + 255) / 256, 256>>>(out);
}

// round 12
// speedup vs baseline: 1.2064x; 1.0360x over previous
#include <cuda_runtime.h>
#include <cuda_bf16.h>
#include <math.h>
#include <stdint.h>

#define NN 100000
#define EE 1600000
#define HH 128
#define GG 256
#define LL 3
#define NB_SCAN ((NN + 1023) / 1024)   // 98
#define NTILES ((NN + 127) / 128)      // 782

// padded k-major bf16 tile in smem: 128 rows x 136 halves (272 B row pitch)
#define RPITCH 272
#define TILE_U4 2176   // 128 * 17 uint4
#define PAIR_B 69632   // bytes per hi+lo pair region
#define HALF_B 34816
#define NSLOT 9

// ---------------- scratch (device globals; no allocation) ----------------
__device__ __align__(16) float g_h[NN * HH];
__device__ __align__(16) float g_t[NN * HH];
__device__ __align__(16) float g_r[NN * HH];
__device__ __align__(16) float g_tmp[NN * HH];
__device__ __align__(16) float g_F4[4][HH * HH];
__device__ __align__(16) float g_c4[4][HH];
__device__ __align__(16) uint4 g_Whi[NSLOT][TILE_U4];
__device__ __align__(16) uint4 g_Wlo[NSLOT][TILE_U4];
__device__ __align__(16) uint4 g_s0h[NN * 16];
__device__ __align__(16) uint4 g_s0l[NN * 16];
__device__ __align__(16) uint4 g_s1h[NN * 16];
__device__ __align__(16) uint4 g_s1l[NN * 16];
__device__ int    g_deg[NN];
__device__ int    g_incl[NN];
__device__ int    g_rowptr[NN + 1];
__device__ int    g_cursor[NN];
__device__ int    g_srcs[EE];
__device__ float4 g_ppf[EE];
__device__ int    g_bsum[128];
__device__ int    g_is64;

__device__ __forceinline__ float* getbuf(int id) {
    switch (id) {
        case 0: return g_h;
        case 1: return g_t;
        case 2: return g_r;
        default: return g_tmp;
    }
}
__device__ __forceinline__ uint4* gs_hi(int id) { return id ? g_s1h : g_s0h; }
__device__ __forceinline__ uint4* gs_lo(int id) { return id ? g_s1l : g_s0l; }

__device__ __forceinline__ int load_idx(const void* p, long long i, int is64) {
    if (is64) return (int)((const long long*)p)[i];
    return ((const int*)p)[i];
}

// ================= mma.sync + cp.async helpers =================
__device__ __forceinline__ uint32_t smem_u32(const void* p) {
    uint32_t a;
    asm("{ .reg .u64 t; cvta.to.shared.u64 t, %1; cvt.u32.u64 %0, t; }" : "=r"(a) : "l"(p));
    return a;
}
__device__ __forceinline__ void ldm4(uint32_t* r, uint32_t addr) {
    asm volatile("ldmatrix.sync.aligned.m8n8.x4.shared.b16 {%0,%1,%2,%3}, [%4];"
        : "=r"(r[0]), "=r"(r[1]), "=r"(r[2]), "=r"(r[3]) : "r"(addr));
}
__device__ __forceinline__ void mma16816(float* d, const uint32_t* a, uint32_t b0, uint32_t b1) {
    asm volatile("mma.sync.aligned.m16n8k16.row.col.f32.bf16.bf16.f32 "
        "{%0,%1,%2,%3}, {%4,%5,%6,%7}, {%8,%9}, {%0,%1,%2,%3};"
        : "+f"(d[0]), "+f"(d[1]), "+f"(d[2]), "+f"(d[3])
        : "r"(a[0]), "r"(a[1]), "r"(a[2]), "r"(a[3]), "r"(b0), "r"(b1));
}
__device__ __forceinline__ void cpa16(uint32_t dst, const void* src, unsigned sz) {
    asm volatile("cp.async.cg.shared.global [%0], [%1], 16, %2;"
        :: "r"(dst), "l"(src), "r"(sz) : "memory");
}
#define CPA_COMMIT() asm volatile("cp.async.commit_group;" ::: "memory")
#define CPA_WAIT(n)  asm volatile("cp.async.wait_group %0;" :: "n"(n) : "memory")

// split helpers
__device__ __forceinline__ void split1(float v, unsigned& h, unsigned& l) {
    __nv_bfloat16 hb = __float2bfloat16(v);
    float rem = v - __bfloat162float(hb);
    __nv_bfloat16 lb = __float2bfloat16(rem);
    h = (unsigned)__bfloat16_as_ushort(hb);
    l = (unsigned)__bfloat16_as_ushort(lb);
}
__device__ __forceinline__ void split8(const float* v, uint4& hi, uint4& lo) {
    unsigned hs[8], ls[8];
#pragma unroll
    for (int j = 0; j < 8; j++) split1(v[j], hs[j], ls[j]);
    hi = make_uint4(hs[0] | (hs[1] << 16), hs[2] | (hs[3] << 16), hs[4] | (hs[5] << 16), hs[6] | (hs[7] << 16));
    lo = make_uint4(ls[0] | (ls[1] << 16), ls[2] | (ls[3] << 16), ls[4] | (ls[5] << 16), ls[6] | (ls[7] << 16));
}
__device__ __forceinline__ void split4_u2(const float4& v, uint2& hi, uint2& lo) {
    unsigned h0, h1, h2, h3, l0, l1, l2, l3;
    split1(v.x, h0, l0); split1(v.y, h1, l1); split1(v.z, h2, l2); split1(v.w, h3, l3);
    hi = make_uint2(h0 | (h1 << 16), h2 | (h3 << 16));
    lo = make_uint2(l0 | (l1 << 16), l2 | (l3 << 16));
}

// MMA over one 128x128 tile: A pair at (aH,aL), B pair at (bH,bL); warp tile 16x64
__device__ __forceinline__ void mma_tile(float d[8][4], uint32_t aH, uint32_t aL,
                                         uint32_t bH, uint32_t bL,
                                         int mrow0, int ncol0, int lane) {
    const int lrow = lane & 15;
    const int lkof = ((lane >> 4) << 3) * 2;
#pragma unroll
    for (int nt = 0; nt < 8; nt++)
#pragma unroll
        for (int j = 0; j < 4; j++) d[nt][j] = 0.f;
#pragma unroll
    for (int kk = 0; kk < 8; kk++) {
        int kb = kk * 32 + lkof;
        uint32_t ah[4], al[4];
        {
            uint32_t off = (mrow0 + lrow) * RPITCH + kb;
            ldm4(ah, aH + off);
            ldm4(al, aL + off);
        }
        uint32_t bh[4][4], bl[4][4];
#pragma unroll
        for (int np = 0; np < 4; np++) {
            uint32_t off = (ncol0 + np * 16 + lrow) * RPITCH + kb;
            ldm4(bh[np], bH + off);
            ldm4(bl[np], bL + off);
        }
#pragma unroll
        for (int np = 0; np < 4; np++) {
            mma16816(d[np * 2],     ah, bh[np][0], bh[np][2]);
            mma16816(d[np * 2],     ah, bl[np][0], bl[np][2]);
            mma16816(d[np * 2],     al, bh[np][0], bh[np][2]);
            mma16816(d[np * 2 + 1], ah, bh[np][1], bh[np][3]);
            mma16816(d[np * 2 + 1], ah, bl[np][1], bl[np][3]);
            mma16816(d[np * 2 + 1], al, bh[np][1], bh[np][3]);
        }
    }
}

// ---------------- dtype detection ----------------
__global__ void k_detect(const void* ei) {
    __shared__ int s_nz;
    if (threadIdx.x == 0) s_nz = 0;
    __syncthreads();
    const int* w = (const int*)ei;
    int v = w[2 * threadIdx.x + 1];
    int v2 = w[2 * (threadIdx.x + 1024) + 1];
    if ((v | v2) != 0) atomicOr(&s_nz, 1);
    __syncthreads();
    if (threadIdx.x == 0) g_is64 = s_nz ? 0 : 1;
}

__global__ void k_init() {
    int i = blockIdx.x * blockDim.x + threadIdx.x;
    if (i < NN) g_deg[i] = 0;
}

__global__ void k_hist(const void* ei) {
    int e = blockIdx.x * blockDim.x + threadIdx.x;
    if (e < EE) {
        int d = load_idx(ei, (long long)EE + e, g_is64);
        atomicAdd(&g_deg[d], 1);
    }
}

__global__ void k_scan1() {
    __shared__ int s[1024];
    int tid = threadIdx.x;
    int i = blockIdx.x * 1024 + tid;
    int v = (i < NN) ? g_deg[i] : 0;
    s[tid] = v;
    __syncthreads();
    for (int off = 1; off < 1024; off <<= 1) {
        int a = (tid >= off) ? s[tid - off] : 0;
        __syncthreads();
        s[tid] += a;
        __syncthreads();
    }
    if (i < NN) g_incl[i] = s[tid];
    if (tid == 1023) g_bsum[blockIdx.x] = s[1023];
}

__global__ void k_scan2() {
    __shared__ int s[128];
    int tid = threadIdx.x;
    s[tid] = (tid < NB_SCAN) ? g_bsum[tid] : 0;
    __syncthreads();
    for (int off = 1; off < 128; off <<= 1) {
        int a = (tid >= off) ? s[tid - off] : 0;
        __syncthreads();
        s[tid] += a;
        __syncthreads();
    }
    if (tid < NB_SCAN) g_bsum[tid] = s[tid];
}

__global__ void k_fin() {
    int tid = threadIdx.x;
    int i = blockIdx.x * 1024 + tid;
    if (i < NN) {
        int off = blockIdx.x ? g_bsum[blockIdx.x - 1] : 0;
        int excl = g_incl[i] - g_deg[i] + off;
        g_rowptr[i] = excl;
        g_cursor[i] = excl;
    }
    if (i == 0) g_rowptr[NN] = EE;
}

__device__ __forceinline__ float dot3(float ax, float ay, float az, float bx, float by, float bz) {
    return ax * bx + ay * by + az * bz;
}
__device__ __forceinline__ float crossnorm(float ax, float ay, float az, float bx, float by, float bz) {
    float cx = ay * bz - az * by;
    float cy = az * bx - ax * bz;
    float cz = ax * by - ay * bx;
    return sqrtf(cx * cx + cy * cy + cz * cz);
}

__global__ void k_scatter(const void* ei, const float* pos) {
    int e = blockIdx.x * blockDim.x + threadIdx.x;
    if (e >= EE) return;
    int is64 = g_is64;
    int s = load_idx(ei, e, is64);
    int d = load_idx(ei, (long long)EE + e, is64);
    float pix = pos[3 * d], piy = pos[3 * d + 1], piz = pos[3 * d + 2];
    float pjx = pos[3 * s], pjy = pos[3 * s + 1], pjz = pos[3 * s + 2];
    float nin = sqrtf(pix * pix + piy * piy + piz * piz) + 1e-12f;
    float njn = sqrtf(pjx * pjx + pjy * pjy + pjz * pjz) + 1e-12f;
    float nix = pix / nin, niy = piy / nin, niz = piz / nin;
    float njx = pjx / njn, njy = pjy / njn, njz = pjz / njn;
    float dx = pjx - pix, dy = pjy - piy, dz = pjz - piz;
    float f0 = sqrtf(dx * dx + dy * dy + dz * dz);
    float f1 = atan2f(crossnorm(nix, niy, niz, dx, dy, dz), dot3(nix, niy, niz, dx, dy, dz));
    float f2 = atan2f(crossnorm(njx, njy, njz, dx, dy, dz), dot3(njx, njy, njz, dx, dy, dz));
    float f3 = atan2f(crossnorm(nix, niy, niz, njx, njy, njz), dot3(nix, niy, niz, njx, njy, njz));
    int slot = atomicAdd(&g_cursor[d], 1);
    g_srcs[slot] = s;
    g_ppf[slot] = make_float4(f0, f1, f2, f3);
}

// ---------------- g_F4[fidx] = A@B, g_c4[fidx] = v@B ----------------
__global__ void k_combine(const float* A, const float* B, const float* v, int fidx) {
    int col = threadIdx.x;
    int row = blockIdx.x;
    if (row < 128) {
        float s = 0.f;
        for (int k = 0; k < 128; k++) s = fmaf(A[row * 128 + k], B[k * 128 + col], s);
        g_F4[fidx][row * 128 + col] = s;
    } else {
        float s = 0.f;
        for (int k = 0; k < 128; k++) s = fmaf(v[k], B[k * 128 + col], s);
        g_c4[fidx][col] = s;
    }
}

// ---------------- split all 9 weight slots ----------------
// slots: 0 = F0; 1..3 = F_{1+l}; 4..6 = gW2_l; 7..8 = W1h_{l+1}
__global__ void k_split_all(const float* lW1, const float* gW2) {
    int g = blockIdx.x;
    int slot = g >> 3;
    int i = (g & 7) * 256 + threadIdx.x;
    const float* src;
    if (slot <= 3) src = g_F4[slot];
    else if (slot <= 6) src = gW2 + (slot - 4) * 128 * 128;
    else src = lW1 + (slot - 6) * 132 * 128;
    int n = i >> 4, kg = i & 15;
    float v[8];
#pragma unroll
    for (int j = 0; j < 8; j++) v[j] = src[(kg * 8 + j) * 128 + n];
    uint4 hi, lo;
    split8(v, hi, lo);
    g_Whi[slot][n * 17 + kg] = hi;
    g_Wlo[slot][n * 17 + kg] = lo;
}

__device__ __forceinline__ void issue_copy512(uint32_t aH, uint32_t aL,
                                              const uint4* Xhi, const uint4* Xlo,
                                              int row0, int nrows, int tid) {
#pragma unroll
    for (int i = tid; i < 2048; i += 512) {
        int row = i >> 4, grp = i & 15;
        int r = row0 + row;
        unsigned sz = (r < nrows) ? 16u : 0u;
        long long rc = (r < nrows) ? r : 0;
        uint32_t off = (uint32_t)(row * RPITCH + grp * 16);
        cpa16(aH + off, &Xhi[rc * 16 + grp], sz);
        cpa16(aL + off, &Xlo[rc * 16 + grp], sz);
    }
}

// ---------------- pipelined single-GEMM (used for t0, t1, t2) ----------------
// BMODE: 0 none, 1 bias (bias==nullptr -> g_c4[cidx]); output fp32 buf yid
#define SM_BHI 0
#define SM_A0 69632
#define SM_A1 139264
#define SM_BYTES 208896

template <int BMODE>
__global__ void __launch_bounds__(512, 1) k_mmagemm(int ip, int wslot, int cidx,
                                                    const float* bias, int yid, int nrows) {
    extern __shared__ char sm[];
    const uint4* Xhi = gs_hi(ip);
    const uint4* Xlo = gs_lo(ip);
    float* Y = getbuf(yid);
    const float* cvec = g_c4[cidx];

    int tid = threadIdx.x;
    int wid = tid >> 5;
    int lane = tid & 31;

    uint4* bhi_s = (uint4*)(sm + SM_BHI);
    uint4* blo_s = (uint4*)(sm + SM_BHI + HALF_B);
    for (int i = tid; i < TILE_U4; i += 512) {
        bhi_s[i] = g_Whi[wslot][i];
        blo_s[i] = g_Wlo[wslot][i];
    }

    const int mrow0 = (wid & 7) * 16;
    const int ncol0 = (wid >> 3) * 64;

    uint32_t a0h = smem_u32(sm + SM_A0), a0l = a0h + HALF_B;
    uint32_t a1h = smem_u32(sm + SM_A1), a1l = a1h + HALF_B;
    uint32_t bH = smem_u32(sm + SM_BHI), bL = bH + HALF_B;

    int tile0 = blockIdx.x;
    if (tile0 < NTILES) {
        issue_copy512(a0h, a0l, Xhi, Xlo, tile0 * 128, nrows, tid);
        CPA_COMMIT();
    }

    int it = 0;
    for (int tile = tile0; tile < NTILES; tile += gridDim.x, it++) {
        int par = it & 1;
        uint32_t aH = par ? a1h : a0h;
        uint32_t aL = par ? a1l : a0l;
        int nxt = tile + gridDim.x;
        if (nxt < NTILES) {
            issue_copy512(par ? a0h : a1h, par ? a0l : a1l, Xhi, Xlo, nxt * 128, nrows, tid);
            CPA_COMMIT();
            CPA_WAIT(1);
        } else {
            CPA_WAIT(0);
        }
        __syncthreads();

        int row0 = tile * 128;
        float d[8][4];
        mma_tile(d, aH, aL, bH, bL, mrow0, ncol0, lane);

        int r0 = row0 + mrow0 + (lane >> 2);
        int r1 = r0 + 8;
        int cbase = ncol0 + 2 * (lane & 3);
#pragma unroll
        for (int nt = 0; nt < 8; nt++) {
            int c = cbase + nt * 8;
            float b0 = 0.f, b1 = 0.f;
            if (BMODE >= 1) {
                const float* bp = (bias != nullptr) ? bias : cvec;
                b0 = bp[c]; b1 = bp[c + 1];
            }
            if (r0 < nrows)
                *(float2*)&Y[(long long)r0 * 128 + c] = make_float2(d[nt][0] + b0, d[nt][1] + b1);
            if (r1 < nrows)
                *(float2*)&Y[(long long)r1 * 128 + c] = make_float2(d[nt][2] + b0, d[nt][3] + b1);
        }
        __syncthreads();
    }
}

// ---------------- fused u+h GEMM ----------------
// u = relu(r@F + gb1 + deg*c)  (in-smem), h = relu(u@gW2 + gb2)
// LAST: write h fp32 to buf0; else split h to pair 1.
#define UH_W1 0
#define UH_W2 69632
#define UH_WK 139264

template <bool LAST>
__global__ void __launch_bounds__(512, 1) k_uh(int ws1, int ws2, int cidx,
                                               const float* gb1, const float* gb2, int nrows) {
    extern __shared__ char sm[];
    const uint4* Xhi = g_s0h;
    const uint4* Xlo = g_s0l;
    float* Y = g_h;   // buf0
    ushort2* Ohi = (ushort2*)g_s1h;
    ushort2* Olo = (ushort2*)g_s1l;
    const float* cvec = g_c4[cidx];

    int tid = threadIdx.x;
    int wid = tid >> 5;
    int lane = tid & 31;

    // persistent weights
    uint4* w1h = (uint4*)(sm + UH_W1);
    uint4* w1l = (uint4*)(sm + UH_W1 + HALF_B);
    uint4* w2h = (uint4*)(sm + UH_W2);
    uint4* w2l = (uint4*)(sm + UH_W2 + HALF_B);
    for (int i = tid; i < TILE_U4; i += 512) {
        w1h[i] = g_Whi[ws1][i];
        w1l[i] = g_Wlo[ws1][i];
        w2h[i] = g_Whi[ws2][i];
        w2l[i] = g_Wlo[ws2][i];
    }

    const int mrow0 = (wid & 7) * 16;
    const int ncol0 = (wid >> 3) * 64;

    uint32_t wkH = smem_u32(sm + UH_WK), wkL = wkH + HALF_B;
    uint32_t b1H = smem_u32(sm + UH_W1), b1L = b1H + HALF_B;
    uint32_t b2H = smem_u32(sm + UH_W2), b2L = b2H + HALF_B;

    for (int tile = blockIdx.x; tile < NTILES; tile += gridDim.x) {
        int row0 = tile * 128;
        __syncthreads();   // protect WORK from previous tile readers
        issue_copy512(wkH, wkL, Xhi, Xlo, row0, nrows, tid);
        CPA_COMMIT();
        CPA_WAIT(0);
        __syncthreads();

        // ---- MMA1: u = relu(r@F + gb1 + deg*c) ----
        float d[8][4];
        mma_tile(d, wkH, wkL, b1H, b1L, mrow0, ncol0, lane);
        __syncthreads();   // all warps done reading r tile

        int lr0 = mrow0 + (lane >> 2);
        int lr1 = lr0 + 8;
        int gr0 = row0 + lr0, gr1 = row0 + lr1;
        float sc0 = (gr0 < nrows) ? (float)g_deg[gr0] : 0.f;
        float sc1 = (gr1 < nrows) ? (float)g_deg[gr1] : 0.f;
        int cbase = ncol0 + 2 * (lane & 3);
#pragma unroll
        for (int nt = 0; nt < 8; nt++) {
            int c = cbase + nt * 8;
            float b0 = gb1[c], b1 = gb1[c + 1];
            float c0 = cvec[c], c1 = cvec[c + 1];
            float u0 = fmaxf(d[nt][0] + b0 + sc0 * c0, 0.f);
            float u1 = fmaxf(d[nt][1] + b1 + sc0 * c1, 0.f);
            float u2 = fmaxf(d[nt][2] + b0 + sc1 * c0, 0.f);
            float u3 = fmaxf(d[nt][3] + b1 + sc1 * c1, 0.f);
            unsigned h0, h1, h2, h3, l0, l1, l2, l3;
            split1(u0, h0, l0); split1(u1, h1, l1);
            split1(u2, h2, l2); split1(u3, h3, l3);
            uint32_t off0 = lr0 * RPITCH + c * 2;
            uint32_t off1 = lr1 * RPITCH + c * 2;
            *(ushort2*)(sm + UH_WK + off0) = make_ushort2((unsigned short)h0, (unsigned short)h1);
            *(ushort2*)(sm + UH_WK + HALF_B + off0) = make_ushort2((unsigned short)l0, (unsigned short)l1);
            *(ushort2*)(sm + UH_WK + off1) = make_ushort2((unsigned short)h2, (unsigned short)h3);
            *(ushort2*)(sm + UH_WK + HALF_B + off1) = make_ushort2((unsigned short)l2, (unsigned short)l3);
        }
        __syncthreads();   // u tile visible to all

        // ---- MMA2: h = relu(u@gW2 + gb2) ----
        mma_tile(d, wkH, wkL, b2H, b2L, mrow0, ncol0, lane);

#pragma unroll
        for (int nt = 0; nt < 8; nt++) {
            int c = cbase + nt * 8;
            float b0 = gb2[c], b1 = gb2[c + 1];
            if (gr0 < nrows) {
                float v0 = fmaxf(d[nt][0] + b0, 0.f);
                float v1 = fmaxf(d[nt][1] + b1, 0.f);
                if (LAST) {
                    *(float2*)&Y[(long long)gr0 * 128 + c] = make_float2(v0, v1);
                } else {
                    unsigned h0, h1, l0, l1;
                    split1(v0, h0, l0); split1(v1, h1, l1);
                    long long idx = (long long)gr0 * 64 + (c >> 1);
                    Ohi[idx] = make_ushort2((unsigned short)h0, (unsigned short)h1);
                    Olo[idx] = make_ushort2((unsigned short)l0, (unsigned short)l1);
                }
            }
            if (gr1 < nrows) {
                float v2 = fmaxf(d[nt][2] + b0, 0.f);
                float v3 = fmaxf(d[nt][3] + b1, 0.f);
                if (LAST) {
                    *(float2*)&Y[(long long)gr1 * 128 + c] = make_float2(v2, v3);
                } else {
                    unsigned h2, h3, l2, l3;
                    split1(v2, h2, l2); split1(v3, h3, l3);
                    long long idx = (long long)gr1 * 64 + (c >> 1);
                    Ohi[idx] = make_ushort2((unsigned short)h2, (unsigned short)h3);
                    Olo[idx] = make_ushort2((unsigned short)l2, (unsigned short)l3);
                }
            }
        }
    }
}

// ---------------- small GEMM (K=16 node in + heads); optional split output ----------------
template <int K, int M, int BMODE, bool RELU, bool OSPLIT>
__global__ void k_gemm(int xid, const float* Xext,
                       const float* W, const float* bias,
                       int yid, int op, int nrows) {
    constexpr int NT = 64;
    constexpr int CG = M / 4;
    constexpr int NG = 256 / CG;
    constexpr int NPT = NT / NG;
    constexpr int KC = 16;
    __shared__ float Ws[KC * M];
    __shared__ float Xs[NT * K];

    const float* X = (xid >= 0) ? getbuf(xid) : Xext;
    float* Y = getbuf(yid);
    uint2* Ohi = (uint2*)gs_hi(op);
    uint2* Olo = (uint2*)gs_lo(op);

    int tid = threadIdx.x;
    const int c = tid % CG;
    const int g = tid / CG;
    const float4* Ws4 = (const float4*)Ws;
    int ntiles = (nrows + NT - 1) / NT;

    for (int tile = blockIdx.x; tile < ntiles; tile += gridDim.x) {
        int row0 = tile * NT;
        __syncthreads();
        for (int i = tid; i < NT * K; i += 256) {
            int rr = i / K, kk = i % K;
            int r = row0 + rr;
            Xs[i] = (r < nrows) ? X[(long long)r * K + kk] : 0.f;
        }
        float4 acc[NPT];
#pragma unroll
        for (int r = 0; r < NPT; r++) acc[r] = make_float4(0.f, 0.f, 0.f, 0.f);

        for (int kc0 = 0; kc0 < K; kc0 += KC) {
            __syncthreads();
            for (int i = tid; i < KC * M; i += 256) Ws[i] = W[kc0 * M + i];
            __syncthreads();
#pragma unroll
            for (int k = 0; k < KC; k++) {
                float4 w = Ws4[k * CG + c];
#pragma unroll
                for (int r = 0; r < NPT; r++) {
                    float xv = Xs[(g * NPT + r) * K + kc0 + k];
                    acc[r].x = fmaf(xv, w.x, acc[r].x);
                    acc[r].y = fmaf(xv, w.y, acc[r].y);
                    acc[r].z = fmaf(xv, w.z, acc[r].z);
                    acc[r].w = fmaf(xv, w.w, acc[r].w);
                }
            }
        }
        float4 bv = make_float4(0.f, 0.f, 0.f, 0.f);
        if (BMODE >= 1) bv = ((const float4*)bias)[c];
#pragma unroll
        for (int r = 0; r < NPT; r++) {
            int row = row0 + g * NPT + r;
            if (row < nrows) {
                float4 v;
                v.x = acc[r].x + bv.x;
                v.y = acc[r].y + bv.y;
                v.z = acc[r].z + bv.z;
                v.w = acc[r].w + bv.w;
                if (RELU) {
                    v.x = fmaxf(v.x, 0.f);
                    v.y = fmaxf(v.y, 0.f);
                    v.z = fmaxf(v.z, 0.f);
                    v.w = fmaxf(v.w, 0.f);
                }
                if (OSPLIT) {
                    uint2 hi, lo;
                    split4_u2(v, hi, lo);
                    Ohi[(long long)row * (M / 4) + c] = hi;
                    Olo[(long long)row * (M / 4) + c] = lo;
                } else {
                    ((float4*)Y)[(long long)row * CG + c] = v;
                }
            }
        }
    }
}

// ---------------- edge gather: split output into pair 0 ----------------
__global__ void k_gather(const float* W1p, const float* b1) {
    int lane = threadIdx.x & 31;
    int wid = (blockIdx.x * blockDim.x + threadIdx.x) >> 5;
    int nwarps = (gridDim.x * blockDim.x) >> 5;
    const float4* W4 = (const float4*)W1p;
    float4 w0 = W4[0 * 32 + lane];
    float4 w1 = W4[1 * 32 + lane];
    float4 w2 = W4[2 * 32 + lane];
    float4 w3 = W4[3 * 32 + lane];
    float4 bb = ((const float4*)b1)[lane];
    const float4* t4 = (const float4*)g_t;
    uint2* Ohi = (uint2*)g_s0h;
    uint2* Olo = (uint2*)g_s0l;
    for (int node = wid; node < NN; node += nwarps) {
        int s0 = g_rowptr[node];
        int s1 = g_rowptr[node + 1];
        float4 acc = make_float4(0.f, 0.f, 0.f, 0.f);
        for (int s = s0; s < s1; s++) {
            int src = g_srcs[s];
            float4 pf = g_ppf[s];
            float4 tv = t4[(long long)src * 32 + lane];
            float4 h;
            h.x = bb.x + tv.x;
            h.y = bb.y + tv.y;
            h.z = bb.z + tv.z;
            h.w = bb.w + tv.w;
            h.x = fmaf(pf.x, w0.x, h.x); h.y = fmaf(pf.x, w0.y, h.y); h.z = fmaf(pf.x, w0.z, h.z); h.w = fmaf(pf.x, w0.w, h.w);
            h.x = fmaf(pf.y, w1.x, h.x); h.y = fmaf(pf.y, w1.y, h.y); h.z = fmaf(pf.y, w1.z, h.z); h.w = fmaf(pf.y, w1.w, h.w);
            h.x = fmaf(pf.z, w2.x, h.x); h.y = fmaf(pf.z, w2.y, h.y); h.z = fmaf(pf.z, w2.z, h.z); h.w = fmaf(pf.z, w2.w, h.w);
            h.x = fmaf(pf.w, w3.x, h.x); h.y = fmaf(pf.w, w3.y, h.y); h.z = fmaf(pf.w, w3.z, h.z); h.w = fmaf(pf.w, w3.w, h.w);
            acc.x += fmaxf(h.x, 0.f);
            acc.y += fmaxf(h.y, 0.f);
            acc.z += fmaxf(h.z, 0.f);
            acc.w += fmaxf(h.w, 0.f);
        }
        uint2 hi, lo;
        split4_u2(acc, hi, lo);
        Ohi[(long long)node * 32 + lane] = hi;
        Olo[(long long)node * 32 + lane] = lo;
    }
}

// ---------------- per-graph reduction: one block per graph, no atomics ----------------
__global__ void k_gout(const void* batch, float* out) {
    int g = blockIdx.x;
    int is64 = g_is64;
    int lo = 0, hi = NN;
    while (lo < hi) { int m = (lo + hi) >> 1; if (load_idx(batch, m, is64) < g) lo = m + 1; else hi = m; }
    int start = lo;
    int lo2 = start, hi2 = NN;
    while (lo2 < hi2) { int m = (lo2 + hi2) >> 1; if (load_idx(batch, m, is64) < g + 1) lo2 = m + 1; else hi2 = m; }
    int end = lo2;
    int tid = threadIdx.x, col = tid & 15, gy = tid >> 4;
    float s = 0.f;
    for (int n = start + gy; n < end; n += 16) s += g_t[(long long)n * 16 + col];
    __shared__ float sm[16][16];
    sm[gy][col] = s;
    __syncthreads();
    if (gy == 0) {
        float tot = 0.f;
#pragma unroll
        for (int k = 0; k < 16; k++) tot += sm[k][col];
        out[g * 16 + col] = tot;
    }
}

// ---------------- launch ----------------
extern "C" void kernel_launch(void* const* d_in, const int* in_sizes, int n_in,
                              void* d_out, int out_size) {
    const float* x     = (const float*)d_in[0];
    const float* pos   = (const float*)d_in[1];
    const void*  ei    = d_in[2];
    const void*  batch = d_in[3];
    const float* nW1 = (const float*)d_in[4];
    const float* nb1 = (const float*)d_in[5];
    const float* nW2 = (const float*)d_in[6];
    const float* nb2 = (const float*)d_in[7];
    const float* lW1 = (const float*)d_in[8];
    const float* lb1 = (const float*)d_in[9];
    const float* lW2 = (const float*)d_in[10];
    const float* lb2 = (const float*)d_in[11];
    const float* gW1 = (const float*)d_in[12];
    const float* gb1 = (const float*)d_in[13];
    const float* gW2 = (const float*)d_in[14];
    const float* gb2 = (const float*)d_in[15];
    const float* l1W = (const float*)d_in[16];
    const float* l1b = (const float*)d_in[17];
    const float* l2W = (const float*)d_in[18];
    const float* l2b = (const float*)d_in[19];
    float* out = (float*)d_out;

    cudaFuncSetAttribute(k_mmagemm<1>, cudaFuncAttributeMaxDynamicSharedMemorySize, SM_BYTES);
    cudaFuncSetAttribute(k_mmagemm<0>, cudaFuncAttributeMaxDynamicSharedMemorySize, SM_BYTES);
    cudaFuncSetAttribute(k_uh<false>,  cudaFuncAttributeMaxDynamicSharedMemorySize, SM_BYTES);
    cudaFuncSetAttribute(k_uh<true>,   cudaFuncAttributeMaxDynamicSharedMemorySize, SM_BYTES);

    const int GB = 296;
    const int GT = 148;

    k_detect<<<1, 1024>>>(ei);
    k_init<<<(NN + 255) / 256, 256>>>();
    k_hist<<<(EE + 255) / 256, 256>>>(ei);
    k_scan1<<<NB_SCAN, 1024>>>();
    k_scan2<<<1, 128>>>();
    k_fin<<<NB_SCAN, 1024>>>();
    k_scatter<<<(EE + 255) / 256, 256>>>(ei, pos);

    // ---- weight prep ----
    k_combine<<<129, 128>>>(nW2, lW1 + 0 * 132 * 128, nb2, 0);
    for (int l = 0; l < LL; l++)
        k_combine<<<129, 128>>>(lW2 + l * 128 * 128, gW1 + l * 128 * 128, lb2 + l * 128, 1 + l);
    k_split_all<<<NSLOT * 8, 256>>>(lW1, gW2);

    // ---- main chain ----
    // q = relu(x@nW1 + nb1) -> split pair 0
    k_gemm<16, 128, 1, true, true><<<GB, 256>>>(-1, x, nW1, nb1, 3, 0, NN);
    // t0 = q@F0 + c0 -> buf1 (fp32)
    k_mmagemm<1><<<GT, 512, SM_BYTES>>>(0, 0, 0, nullptr, 1, NN);

    for (int l = 0; l < LL; l++) {
        const float* W1p = lW1 + l * 132 * 128 + 128 * 128;
        // r = gather(t=buf1) -> split pair 0
        k_gather<<<1184, 256>>>(W1p, lb1 + l * 128);
        if (l + 1 < LL) {
            // u,h fused -> split pair 1
            k_uh<false><<<GT, 512, SM_BYTES>>>(1 + l, 4 + l, 1 + l, gb1 + l * 128, gb2 + l * 128, NN);
            // t_{l+1} = h@W1h_{l+1} -> buf1 (fp32)
            k_mmagemm<0><<<GT, 512, SM_BYTES>>>(1, 7 + l, 0, nullptr, 1, NN);
        } else {
            // u,h fused, final h -> buf0 (fp32)
            k_uh<true><<<GT, 512, SM_BYTES>>>(1 + l, 4 + l, 1 + l, gb1 + l * 128, gb2 + l * 128, NN);
        }
    }

    // head: buf0 -> buf3 -> buf1 -> out
    k_gemm<128, 64, 1, true, false><<<GB, 256>>>(0, nullptr, l1W, l1b, 3, 0, NN);
    k_gemm<64, 16, 1, false, false><<<GB, 256>>>(3, nullptr, l2W, l2b, 1, 0, NN);
    k_gout<<<GG, 256>>>(batch, out);
}

// round 13
// speedup vs baseline: 1.2617x; 1.0458x over previous
#include <cuda_runtime.h>
#include <cuda_bf16.h>
#include <math.h>
#include <stdint.h>

#define NN 100000
#define EE 1600000
#define HH 128
#define GG 256
#define LL 3
#define NB_SCAN ((NN + 1023) / 1024)   // 98
#define NTILES ((NN + 127) / 128)      // 782

// padded k-major bf16 tile in smem: 128 rows x 136 halves (272 B row pitch)
#define RPITCH 272
#define TILE_U4 2176   // 128 * 17 uint4
#define HALF_B 34816
#define NSLOT 9

// ---------------- scratch (device globals; no allocation) ----------------
__device__ __align__(16) float g_h[NN * HH];
__device__ __align__(16) float g_t[NN * HH];
__device__ __align__(16) float g_tmp[NN * HH];
__device__ __align__(16) float g_F4[4][HH * HH];
__device__ __align__(16) float g_c4[4][HH];
__device__ __align__(16) uint4 g_Whi[NSLOT][TILE_U4];
__device__ __align__(16) uint4 g_Wlo[NSLOT][TILE_U4];
__device__ __align__(16) uint4 g_s0h[NN * 16];
__device__ __align__(16) uint4 g_s0l[NN * 16];
__device__ __align__(16) float4 g_nrm[NN];
__device__ int    g_deg[NN];
__device__ int    g_incl[NN];
__device__ int    g_rowptr[NN + 1];
__device__ int    g_cursor[NN];
__device__ int    g_srcs[EE];
__device__ float4 g_ppf[EE];
__device__ int    g_bsum[128];
__device__ int    g_is64;

__device__ __forceinline__ float* getbuf(int id) {
    switch (id) {
        case 0: return g_h;
        case 1: return g_t;
        default: return g_tmp;
    }
}

__device__ __forceinline__ int load_idx(const void* p, long long i, int is64) {
    if (is64) return (int)((const long long*)p)[i];
    return ((const int*)p)[i];
}

// ================= mma.sync + cp.async helpers =================
__device__ __forceinline__ uint32_t smem_u32(const void* p) {
    uint32_t a;
    asm("{ .reg .u64 t; cvta.to.shared.u64 t, %1; cvt.u32.u64 %0, t; }" : "=r"(a) : "l"(p));
    return a;
}
__device__ __forceinline__ void ldm4(uint32_t* r, uint32_t addr) {
    asm volatile("ldmatrix.sync.aligned.m8n8.x4.shared.b16 {%0,%1,%2,%3}, [%4];"
        : "=r"(r[0]), "=r"(r[1]), "=r"(r[2]), "=r"(r[3]) : "r"(addr));
}
__device__ __forceinline__ void mma16816(float* d, const uint32_t* a, uint32_t b0, uint32_t b1) {
    asm volatile("mma.sync.aligned.m16n8k16.row.col.f32.bf16.bf16.f32 "
        "{%0,%1,%2,%3}, {%4,%5,%6,%7}, {%8,%9}, {%0,%1,%2,%3};"
        : "+f"(d[0]), "+f"(d[1]), "+f"(d[2]), "+f"(d[3])
        : "r"(a[0]), "r"(a[1]), "r"(a[2]), "r"(a[3]), "r"(b0), "r"(b1));
}
__device__ __forceinline__ void cpa16(uint32_t dst, const void* src, unsigned sz) {
    asm volatile("cp.async.cg.shared.global [%0], [%1], 16, %2;"
        :: "r"(dst), "l"(src), "r"(sz) : "memory");
}
#define CPA_COMMIT() asm volatile("cp.async.commit_group;" ::: "memory")
#define CPA_WAIT(n)  asm volatile("cp.async.wait_group %0;" :: "n"(n) : "memory")

// split helpers
__device__ __forceinline__ void split1(float v, unsigned& h, unsigned& l) {
    __nv_bfloat16 hb = __float2bfloat16(v);
    float rem = v - __bfloat162float(hb);
    __nv_bfloat16 lb = __float2bfloat16(rem);
    h = (unsigned)__bfloat16_as_ushort(hb);
    l = (unsigned)__bfloat16_as_ushort(lb);
}
__device__ __forceinline__ void split8(const float* v, uint4& hi, uint4& lo) {
    unsigned hs[8], ls[8];
#pragma unroll
    for (int j = 0; j < 8; j++) split1(v[j], hs[j], ls[j]);
    hi = make_uint4(hs[0] | (hs[1] << 16), hs[2] | (hs[3] << 16), hs[4] | (hs[5] << 16), hs[6] | (hs[7] << 16));
    lo = make_uint4(ls[0] | (ls[1] << 16), ls[2] | (ls[3] << 16), ls[4] | (ls[5] << 16), ls[6] | (ls[7] << 16));
}
__device__ __forceinline__ void split4_u2(const float4& v, uint2& hi, uint2& lo) {
    unsigned h0, h1, h2, h3, l0, l1, l2, l3;
    split1(v.x, h0, l0); split1(v.y, h1, l1); split1(v.z, h2, l2); split1(v.w, h3, l3);
    hi = make_uint2(h0 | (h1 << 16), h2 | (h3 << 16));
    lo = make_uint2(l0 | (l1 << 16), l2 | (l3 << 16));
}

// MMA over one 128x128 tile: A pair (aH,aL), B pair (bH,bL); warp tile 16x64
__device__ __forceinline__ void mma_tile(float d[8][4], uint32_t aH, uint32_t aL,
                                         uint32_t bH, uint32_t bL,
                                         int mrow0, int ncol0, int lane) {
    const int lrow = lane & 15;
    const int lkof = ((lane >> 4) << 3) * 2;
#pragma unroll
    for (int nt = 0; nt < 8; nt++)
#pragma unroll
        for (int j = 0; j < 4; j++) d[nt][j] = 0.f;
#pragma unroll
    for (int kk = 0; kk < 8; kk++) {
        int kb = kk * 32 + lkof;
        uint32_t ah[4], al[4];
        {
            uint32_t off = (mrow0 + lrow) * RPITCH + kb;
            ldm4(ah, aH + off);
            ldm4(al, aL + off);
        }
        uint32_t bh[4][4], bl[4][4];
#pragma unroll
        for (int np = 0; np < 4; np++) {
            uint32_t off = (ncol0 + np * 16 + lrow) * RPITCH + kb;
            ldm4(bh[np], bH + off);
            ldm4(bl[np], bL + off);
        }
#pragma unroll
        for (int np = 0; np < 4; np++) {
            mma16816(d[np * 2],     ah, bh[np][0], bh[np][2]);
            mma16816(d[np * 2],     ah, bl[np][0], bl[np][2]);
            mma16816(d[np * 2],     al, bh[np][0], bh[np][2]);
            mma16816(d[np * 2 + 1], ah, bh[np][1], bh[np][3]);
            mma16816(d[np * 2 + 1], ah, bl[np][1], bl[np][3]);
            mma16816(d[np * 2 + 1], al, bh[np][1], bh[np][3]);
        }
    }
}

// ---------------- dtype detection ----------------
__global__ void k_detect(const void* ei) {
    __shared__ int s_nz;
    if (threadIdx.x == 0) s_nz = 0;
    __syncthreads();
    const int* w = (const int*)ei;
    int v = w[2 * threadIdx.x + 1];
    int v2 = w[2 * (threadIdx.x + 1024) + 1];
    if ((v | v2) != 0) atomicOr(&s_nz, 1);
    __syncthreads();
    if (threadIdx.x == 0) g_is64 = s_nz ? 0 : 1;
}

// init deg + precompute normals
__global__ void k_init(const float* pos) {
    int i = blockIdx.x * blockDim.x + threadIdx.x;
    if (i < NN) {
        g_deg[i] = 0;
        float px = pos[3 * i], py = pos[3 * i + 1], pz = pos[3 * i + 2];
        float n = sqrtf(px * px + py * py + pz * pz) + 1e-12f;
        g_nrm[i] = make_float4(px / n, py / n, pz / n, 0.f);
    }
}

__global__ void k_hist(const void* ei) {
    int e = blockIdx.x * blockDim.x + threadIdx.x;
    if (e < EE) {
        int d = load_idx(ei, (long long)EE + e, g_is64);
        atomicAdd(&g_deg[d], 1);
    }
}

__global__ void k_scan1() {
    __shared__ int s[1024];
    int tid = threadIdx.x;
    int i = blockIdx.x * 1024 + tid;
    int v = (i < NN) ? g_deg[i] : 0;
    s[tid] = v;
    __syncthreads();
    for (int off = 1; off < 1024; off <<= 1) {
        int a = (tid >= off) ? s[tid - off] : 0;
        __syncthreads();
        s[tid] += a;
        __syncthreads();
    }
    if (i < NN) g_incl[i] = s[tid];
    if (tid == 1023) g_bsum[blockIdx.x] = s[1023];
}

__global__ void k_scan2() {
    __shared__ int s[128];
    int tid = threadIdx.x;
    s[tid] = (tid < NB_SCAN) ? g_bsum[tid] : 0;
    __syncthreads();
    for (int off = 1; off < 128; off <<= 1) {
        int a = (tid >= off) ? s[tid - off] : 0;
        __syncthreads();
        s[tid] += a;
        __syncthreads();
    }
    if (tid < NB_SCAN) g_bsum[tid] = s[tid];
}

__global__ void k_fin() {
    int tid = threadIdx.x;
    int i = blockIdx.x * 1024 + tid;
    if (i < NN) {
        int off = blockIdx.x ? g_bsum[blockIdx.x - 1] : 0;
        int excl = g_incl[i] - g_deg[i] + off;
        g_rowptr[i] = excl;
        g_cursor[i] = excl;
    }
    if (i == 0) g_rowptr[NN] = EE;
}

__device__ __forceinline__ float dot3(float ax, float ay, float az, float bx, float by, float bz) {
    return ax * bx + ay * by + az * bz;
}
__device__ __forceinline__ float crossnorm(float ax, float ay, float az, float bx, float by, float bz) {
    float cx = ay * bz - az * by;
    float cy = az * bx - ax * bz;
    float cz = ax * by - ay * bx;
    return sqrtf(cx * cx + cy * cy + cz * cz);
}

__global__ void k_scatter(const void* ei, const float* pos) {
    int e = blockIdx.x * blockDim.x + threadIdx.x;
    if (e >= EE) return;
    int is64 = g_is64;
    int s = load_idx(ei, e, is64);
    int d = load_idx(ei, (long long)EE + e, is64);
    float pix = pos[3 * d], piy = pos[3 * d + 1], piz = pos[3 * d + 2];
    float pjx = pos[3 * s], pjy = pos[3 * s + 1], pjz = pos[3 * s + 2];
    float4 ni = g_nrm[d];
    float4 nj = g_nrm[s];
    float dx = pjx - pix, dy = pjy - piy, dz = pjz - piz;
    float f0 = sqrtf(dx * dx + dy * dy + dz * dz);
    float f1 = atan2f(crossnorm(ni.x, ni.y, ni.z, dx, dy, dz), dot3(ni.x, ni.y, ni.z, dx, dy, dz));
    float f2 = atan2f(crossnorm(nj.x, nj.y, nj.z, dx, dy, dz), dot3(nj.x, nj.y, nj.z, dx, dy, dz));
    float f3 = atan2f(crossnorm(ni.x, ni.y, ni.z, nj.x, nj.y, nj.z), dot3(ni.x, ni.y, ni.z, nj.x, nj.y, nj.z));
    int slot = atomicAdd(&g_cursor[d], 1);
    g_srcs[slot] = s;
    g_ppf[slot] = make_float4(f0, f1, f2, f3);
}

// ---------------- g_F4[fidx] = A@B, g_c4[fidx] = v@B ----------------
__global__ void k_combine(const float* A, const float* B, const float* v, int fidx) {
    int col = threadIdx.x;
    int row = blockIdx.x;
    if (row < 128) {
        float s = 0.f;
        for (int k = 0; k < 128; k++) s = fmaf(A[row * 128 + k], B[k * 128 + col], s);
        g_F4[fidx][row * 128 + col] = s;
    } else {
        float s = 0.f;
        for (int k = 0; k < 128; k++) s = fmaf(v[k], B[k * 128 + col], s);
        g_c4[fidx][col] = s;
    }
}

// ---------------- split all 9 weight slots ----------------
// slots: 0 = F0; 1..3 = F_{1+l}; 4..6 = gW2_l; 7..8 = W1h_{l+1}
__global__ void k_split_all(const float* lW1, const float* gW2) {
    int g = blockIdx.x;
    int slot = g >> 3;
    int i = (g & 7) * 256 + threadIdx.x;
    const float* src;
    if (slot <= 3) src = g_F4[slot];
    else if (slot <= 6) src = gW2 + (slot - 4) * 128 * 128;
    else src = lW1 + (slot - 6) * 132 * 128;
    int n = i >> 4, kg = i & 15;
    float v[8];
#pragma unroll
    for (int j = 0; j < 8; j++) v[j] = src[(kg * 8 + j) * 128 + n];
    uint4 hi, lo;
    split8(v, hi, lo);
    g_Whi[slot][n * 17 + kg] = hi;
    g_Wlo[slot][n * 17 + kg] = lo;
}

__device__ __forceinline__ void issue_copy512(uint32_t aH, uint32_t aL,
                                              const uint4* Xhi, const uint4* Xlo,
                                              int row0, int nrows, int tid) {
#pragma unroll
    for (int i = tid; i < 2048; i += 512) {
        int row = i >> 4, grp = i & 15;
        int r = row0 + row;
        unsigned sz = (r < nrows) ? 16u : 0u;
        long long rc = (r < nrows) ? r : 0;
        uint32_t off = (uint32_t)(row * RPITCH + grp * 16);
        cpa16(aH + off, &Xhi[rc * 16 + grp], sz);
        cpa16(aL + off, &Xlo[rc * 16 + grp], sz);
    }
}

__device__ __forceinline__ void copy_w(uint32_t dH, uint32_t dL, int slot, int tid) {
    const uint4* sh = g_Whi[slot];
    const uint4* sl = g_Wlo[slot];
    for (int i = tid; i < TILE_U4; i += 512) {
        cpa16(dH + (uint32_t)(i * 16), &sh[i], 16u);
        cpa16(dL + (uint32_t)(i * 16), &sl[i], 16u);
    }
}

// ---------------- pipelined single-GEMM (t0 only) ----------------
#define SM_BHI 0
#define SM_A0 69632
#define SM_A1 139264
#define SM_BYTES 208896

__global__ void __launch_bounds__(512, 1) k_mmagemm(int wslot, int cidx, int yid, int nrows) {
    extern __shared__ char sm[];
    const uint4* Xhi = g_s0h;
    const uint4* Xlo = g_s0l;
    float* Y = getbuf(yid);
    const float* cvec = g_c4[cidx];

    int tid = threadIdx.x;
    int wid = tid >> 5;
    int lane = tid & 31;

    uint4* bhi_s = (uint4*)(sm + SM_BHI);
    uint4* blo_s = (uint4*)(sm + SM_BHI + HALF_B);
    for (int i = tid; i < TILE_U4; i += 512) {
        bhi_s[i] = g_Whi[wslot][i];
        blo_s[i] = g_Wlo[wslot][i];
    }

    const int mrow0 = (wid & 7) * 16;
    const int ncol0 = (wid >> 3) * 64;

    uint32_t a0h = smem_u32(sm + SM_A0), a0l = a0h + HALF_B;
    uint32_t a1h = smem_u32(sm + SM_A1), a1l = a1h + HALF_B;
    uint32_t bH = smem_u32(sm + SM_BHI), bL = bH + HALF_B;

    int tile0 = blockIdx.x;
    if (tile0 < NTILES) {
        issue_copy512(a0h, a0l, Xhi, Xlo, tile0 * 128, nrows, tid);
        CPA_COMMIT();
    }

    int it = 0;
    for (int tile = tile0; tile < NTILES; tile += gridDim.x, it++) {
        int par = it & 1;
        uint32_t aH = par ? a1h : a0h;
        uint32_t aL = par ? a1l : a0l;
        int nxt = tile + gridDim.x;
        if (nxt < NTILES) {
            issue_copy512(par ? a0h : a1h, par ? a0l : a1l, Xhi, Xlo, nxt * 128, nrows, tid);
            CPA_COMMIT();
            CPA_WAIT(1);
        } else {
            CPA_WAIT(0);
        }
        __syncthreads();

        int row0 = tile * 128;
        float d[8][4];
        mma_tile(d, aH, aL, bH, bL, mrow0, ncol0, lane);

        int r0 = row0 + mrow0 + (lane >> 2);
        int r1 = r0 + 8;
        int cbase = ncol0 + 2 * (lane & 3);
#pragma unroll
        for (int nt = 0; nt < 8; nt++) {
            int c = cbase + nt * 8;
            float b0 = cvec[c], b1 = cvec[c + 1];
            if (r0 < nrows)
                *(float2*)&Y[(long long)r0 * 128 + c] = make_float2(d[nt][0] + b0, d[nt][1] + b1);
            if (r1 < nrows)
                *(float2*)&Y[(long long)r1 * 128 + c] = make_float2(d[nt][2] + b0, d[nt][3] + b1);
        }
        __syncthreads();
    }
}

// ---------------- fused layer kernel: u -> h -> (t | h out) ----------------
// R0: r, then W2.   R1: F, then W1h.   R2: u, then h.
// LAST=false: writes t = h@W1h (fp32) to g_t.  LAST=true: writes h (fp32) to g_h.
template <bool LAST>
__global__ void __launch_bounds__(512, 1) k_layer(int ws1, int ws2, int ws3, int cidx,
                                                  const float* gb1, const float* gb2, int nrows) {
    extern __shared__ char sm[];
    const uint4* Xhi = g_s0h;
    const uint4* Xlo = g_s0l;
    const float* cvec = g_c4[cidx];

    int tid = threadIdx.x;
    int wid = tid >> 5;
    int lane = tid & 31;
    const int mrow0 = (wid & 7) * 16;
    const int ncol0 = (wid >> 3) * 64;

    uint32_t R0h = smem_u32(sm),            R0l = R0h + HALF_B;
    uint32_t R1h = R0h + 69632,             R1l = R1h + HALF_B;
    uint32_t R2h = R0h + 139264,            R2l = R2h + HALF_B;

    for (int tile = blockIdx.x; tile < NTILES; tile += gridDim.x) {
        int row0 = tile * 128;
        // phase 0: r tile -> R0, F -> R1
        issue_copy512(R0h, R0l, Xhi, Xlo, row0, nrows, tid);
        copy_w(R1h, R1l, ws1, tid);
        CPA_COMMIT();
        CPA_WAIT(0);
        __syncthreads();

        // MMA1: u-pre = r@F
        float d[8][4];
        mma_tile(d, R0h, R0l, R1h, R1l, mrow0, ncol0, lane);
        __syncthreads();   // all reads of R0/R1 done

        // prefetch next weights while doing u epilogue
        copy_w(R0h, R0l, ws2, tid);
        if (!LAST) copy_w(R1h, R1l, ws3, tid);
        CPA_COMMIT();

        int lr0 = mrow0 + (lane >> 2);
        int lr1 = lr0 + 8;
        int gr0 = row0 + lr0, gr1 = row0 + lr1;
        float sc0 = (gr0 < nrows) ? (float)g_deg[gr0] : 0.f;
        float sc1 = (gr1 < nrows) ? (float)g_deg[gr1] : 0.f;
        int cbase = ncol0 + 2 * (lane & 3);
#pragma unroll
        for (int nt = 0; nt < 8; nt++) {
            int c = cbase + nt * 8;
            float b0 = gb1[c], b1 = gb1[c + 1];
            float c0 = cvec[c], c1 = cvec[c + 1];
            float u0 = fmaxf(d[nt][0] + b0 + sc0 * c0, 0.f);
            float u1 = fmaxf(d[nt][1] + b1 + sc0 * c1, 0.f);
            float u2 = fmaxf(d[nt][2] + b0 + sc1 * c0, 0.f);
            float u3 = fmaxf(d[nt][3] + b1 + sc1 * c1, 0.f);
            unsigned h0, h1, h2, h3, l0, l1, l2, l3;
            split1(u0, h0, l0); split1(u1, h1, l1);
            split1(u2, h2, l2); split1(u3, h3, l3);
            uint32_t off0 = lr0 * RPITCH + c * 2;
            uint32_t off1 = lr1 * RPITCH + c * 2;
            *(ushort2*)(sm + 139264 + off0) = make_ushort2((unsigned short)h0, (unsigned short)h1);
            *(ushort2*)(sm + 139264 + HALF_B + off0) = make_ushort2((unsigned short)l0, (unsigned short)l1);
            *(ushort2*)(sm + 139264 + off1) = make_ushort2((unsigned short)h2, (unsigned short)h3);
            *(ushort2*)(sm + 139264 + HALF_B + off1) = make_ushort2((unsigned short)l2, (unsigned short)l3);
        }
        CPA_WAIT(0);
        __syncthreads();   // u ready, W2/W1h ready

        // MMA2: h-pre = u@W2
        mma_tile(d, R2h, R2l, R0h, R0l, mrow0, ncol0, lane);
        __syncthreads();   // R2 reads done

        if (LAST) {
            // h epilogue -> g_h fp32
#pragma unroll
            for (int nt = 0; nt < 8; nt++) {
                int c = cbase + nt * 8;
                float b0 = gb2[c], b1 = gb2[c + 1];
                if (gr0 < nrows) {
                    float v0 = fmaxf(d[nt][0] + b0, 0.f);
                    float v1 = fmaxf(d[nt][1] + b1, 0.f);
                    *(float2*)&g_h[(long long)gr0 * 128 + c] = make_float2(v0, v1);
                }
                if (gr1 < nrows) {
                    float v2 = fmaxf(d[nt][2] + b0, 0.f);
                    float v3 = fmaxf(d[nt][3] + b1, 0.f);
                    *(float2*)&g_h[(long long)gr1 * 128 + c] = make_float2(v2, v3);
                }
            }
        } else {
            // h epilogue -> R2 (split)
#pragma unroll
            for (int nt = 0; nt < 8; nt++) {
                int c = cbase + nt * 8;
                float b0 = gb2[c], b1 = gb2[c + 1];
                float v0 = fmaxf(d[nt][0] + b0, 0.f);
                float v1 = fmaxf(d[nt][1] + b1, 0.f);
                float v2 = fmaxf(d[nt][2] + b0, 0.f);
                float v3 = fmaxf(d[nt][3] + b1, 0.f);
                unsigned h0, h1, h2, h3, l0, l1, l2, l3;
                split1(v0, h0, l0); split1(v1, h1, l1);
                split1(v2, h2, l2); split1(v3, h3, l3);
                uint32_t off0 = lr0 * RPITCH + c * 2;
                uint32_t off1 = lr1 * RPITCH + c * 2;
                *(ushort2*)(sm + 139264 + off0) = make_ushort2((unsigned short)h0, (unsigned short)h1);
                *(ushort2*)(sm + 139264 + HALF_B + off0) = make_ushort2((unsigned short)l0, (unsigned short)l1);
                *(ushort2*)(sm + 139264 + off1) = make_ushort2((unsigned short)h2, (unsigned short)h3);
                *(ushort2*)(sm + 139264 + HALF_B + off1) = make_ushort2((unsigned short)l2, (unsigned short)l3);
            }
            __syncthreads();   // h ready

            // MMA3: t = h@W1h
            mma_tile(d, R2h, R2l, R1h, R1l, mrow0, ncol0, lane);
#pragma unroll
            for (int nt = 0; nt < 8; nt++) {
                int c = cbase + nt * 8;
                if (gr0 < nrows)
                    *(float2*)&g_t[(long long)gr0 * 128 + c] = make_float2(d[nt][0], d[nt][1]);
                if (gr1 < nrows)
                    *(float2*)&g_t[(long long)gr1 * 128 + c] = make_float2(d[nt][2], d[nt][3]);
            }
        }
        __syncthreads();   // protect regions before next tile's copies
    }
}

// ---------------- small GEMM (K=16 node in + heads); optional split output ----------------
template <int K, int M, int BMODE, bool RELU, bool OSPLIT>
__global__ void k_gemm(int xid, const float* Xext,
                       const float* W, const float* bias,
                       int yid, int nrows) {
    constexpr int NT = 64;
    constexpr int CG = M / 4;
    constexpr int NG = 256 / CG;
    constexpr int NPT = NT / NG;
    constexpr int KC = 16;
    __shared__ float Ws[KC * M];
    __shared__ float Xs[NT * K];

    const float* X = (xid >= 0) ? getbuf(xid) : Xext;
    float* Y = getbuf(yid);
    uint2* Ohi = (uint2*)g_s0h;
    uint2* Olo = (uint2*)g_s0l;

    int tid = threadIdx.x;
    const int c = tid % CG;
    const int g = tid / CG;
    const float4* Ws4 = (const float4*)Ws;
    int ntiles = (nrows + NT - 1) / NT;

    for (int tile = blockIdx.x; tile < ntiles; tile += gridDim.x) {
        int row0 = tile * NT;
        __syncthreads();
        for (int i = tid; i < NT * K; i += 256) {
            int rr = i / K, kk = i % K;
            int r = row0 + rr;
            Xs[i] = (r < nrows) ? X[(long long)r * K + kk] : 0.f;
        }
        float4 acc[NPT];
#pragma unroll
        for (int r = 0; r < NPT; r++) acc[r] = make_float4(0.f, 0.f, 0.f, 0.f);

        for (int kc0 = 0; kc0 < K; kc0 += KC) {
            __syncthreads();
            for (int i = tid; i < KC * M; i += 256) Ws[i] = W[kc0 * M + i];
            __syncthreads();
#pragma unroll
            for (int k = 0; k < KC; k++) {
                float4 w = Ws4[k * CG + c];
#pragma unroll
                for (int r = 0; r < NPT; r++) {
                    float xv = Xs[(g * NPT + r) * K + kc0 + k];
                    acc[r].x = fmaf(xv, w.x, acc[r].x);
                    acc[r].y = fmaf(xv, w.y, acc[r].y);
                    acc[r].z = fmaf(xv, w.z, acc[r].z);
                    acc[r].w = fmaf(xv, w.w, acc[r].w);
                }
            }
        }
        float4 bv = make_float4(0.f, 0.f, 0.f, 0.f);
        if (BMODE >= 1) bv = ((const float4*)bias)[c];
#pragma unroll
        for (int r = 0; r < NPT; r++) {
            int row = row0 + g * NPT + r;
            if (row < nrows) {
                float4 v;
                v.x = acc[r].x + bv.x;
                v.y = acc[r].y + bv.y;
                v.z = acc[r].z + bv.z;
                v.w = acc[r].w + bv.w;
                if (RELU) {
                    v.x = fmaxf(v.x, 0.f);
                    v.y = fmaxf(v.y, 0.f);
                    v.z = fmaxf(v.z, 0.f);
                    v.w = fmaxf(v.w, 0.f);
                }
                if (OSPLIT) {
                    uint2 hi, lo;
                    split4_u2(v, hi, lo);
                    Ohi[(long long)row * (M / 4) + c] = hi;
                    Olo[(long long)row * (M / 4) + c] = lo;
                } else {
                    ((float4*)Y)[(long long)row * CG + c] = v;
                }
            }
        }
    }
}

// ---------------- edge gather: split output into pair 0 ----------------
__global__ void k_gather(const float* W1p, const float* b1) {
    int lane = threadIdx.x & 31;
    int wid = (blockIdx.x * blockDim.x + threadIdx.x) >> 5;
    int nwarps = (gridDim.x * blockDim.x) >> 5;
    const float4* W4 = (const float4*)W1p;
    float4 w0 = W4[0 * 32 + lane];
    float4 w1 = W4[1 * 32 + lane];
    float4 w2 = W4[2 * 32 + lane];
    float4 w3 = W4[3 * 32 + lane];
    float4 bb = ((const float4*)b1)[lane];
    const float4* t4 = (const float4*)g_t;
    uint2* Ohi = (uint2*)g_s0h;
    uint2* Olo = (uint2*)g_s0l;
    for (int node = wid; node < NN; node += nwarps) {
        int s0 = g_rowptr[node];
        int s1 = g_rowptr[node + 1];
        float4 acc = make_float4(0.f, 0.f, 0.f, 0.f);
        for (int s = s0; s < s1; s++) {
            int src = __ldg(&g_srcs[s]);
            float4 pf = __ldg(&g_ppf[s]);
            float4 tv = __ldg(&t4[(long long)src * 32 + lane]);
            float4 h;
            h.x = bb.x + tv.x;
            h.y = bb.y + tv.y;
            h.z = bb.z + tv.z;
            h.w = bb.w + tv.w;
            h.x = fmaf(pf.x, w0.x, h.x); h.y = fmaf(pf.x, w0.y, h.y); h.z = fmaf(pf.x, w0.z, h.z); h.w = fmaf(pf.x, w0.w, h.w);
            h.x = fmaf(pf.y, w1.x, h.x); h.y = fmaf(pf.y, w1.y, h.y); h.z = fmaf(pf.y, w1.z, h.z); h.w = fmaf(pf.y, w1.w, h.w);
            h.x = fmaf(pf.z, w2.x, h.x); h.y = fmaf(pf.z, w2.y, h.y); h.z = fmaf(pf.z, w2.z, h.z); h.w = fmaf(pf.z, w2.w, h.w);
            h.x = fmaf(pf.w, w3.x, h.x); h.y = fmaf(pf.w, w3.y, h.y); h.z = fmaf(pf.w, w3.z, h.z); h.w = fmaf(pf.w, w3.w, h.w);
            acc.x += fmaxf(h.x, 0.f);
            acc.y += fmaxf(h.y, 0.f);
            acc.z += fmaxf(h.z, 0.f);
            acc.w += fmaxf(h.w, 0.f);
        }
        uint2 hi, lo;
        split4_u2(acc, hi, lo);
        Ohi[(long long)node * 32 + lane] = hi;
        Olo[(long long)node * 32 + lane] = lo;
    }
}

// ---------------- per-graph reduction: one block per graph, no atomics ----------------
__global__ void k_gout(const void* batch, float* out) {
    int g = blockIdx.x;
    int is64 = g_is64;
    int lo = 0, hi = NN;
    while (lo < hi) { int m = (lo + hi) >> 1; if (load_idx(batch, m, is64) < g) lo = m + 1; else hi = m; }
    int start = lo;
    int lo2 = start, hi2 = NN;
    while (lo2 < hi2) { int m = (lo2 + hi2) >> 1; if (load_idx(batch, m, is64) < g + 1) lo2 = m + 1; else hi2 = m; }
    int end = lo2;
    int tid = threadIdx.x, col = tid & 15, gy = tid >> 4;
    float s = 0.f;
    for (int n = start + gy; n < end; n += 16) s += g_t[(long long)n * 16 + col];
    __shared__ float sm[16][16];
    sm[gy][col] = s;
    __syncthreads();
    if (gy == 0) {
        float tot = 0.f;
#pragma unroll
        for (int k = 0; k < 16; k++) tot += sm[k][col];
        out[g * 16 + col] = tot;
    }
}

// ---------------- launch ----------------
extern "C" void kernel_launch(void* const* d_in, const int* in_sizes, int n_in,
                              void* d_out, int out_size) {
    const float* x     = (const float*)d_in[0];
    const float* pos   = (const float*)d_in[1];
    const void*  ei    = d_in[2];
    const void*  batch = d_in[3];
    const float* nW1 = (const float*)d_in[4];
    const float* nb1 = (const float*)d_in[5];
    const float* nW2 = (const float*)d_in[6];
    const float* nb2 = (const float*)d_in[7];
    const float* lW1 = (const float*)d_in[8];
    const float* lb1 = (const float*)d_in[9];
    const float* lW2 = (const float*)d_in[10];
    const float* lb2 = (const float*)d_in[11];
    const float* gW1 = (const float*)d_in[12];
    const float* gb1 = (const float*)d_in[13];
    const float* gW2 = (const float*)d_in[14];
    const float* gb2 = (const float*)d_in[15];
    const float* l1W = (const float*)d_in[16];
    const float* l1b = (const float*)d_in[17];
    const float* l2W = (const float*)d_in[18];
    const float* l2b = (const float*)d_in[19];
    float* out = (float*)d_out;

    cudaFuncSetAttribute(k_mmagemm,      cudaFuncAttributeMaxDynamicSharedMemorySize, SM_BYTES);
    cudaFuncSetAttribute(k_layer<false>, cudaFuncAttributeMaxDynamicSharedMemorySize, SM_BYTES);
    cudaFuncSetAttribute(k_layer<true>,  cudaFuncAttributeMaxDynamicSharedMemorySize, SM_BYTES);

    const int GB = 296;
    const int GT = 148;

    k_detect<<<1, 1024>>>(ei);
    k_init<<<(NN + 255) / 256, 256>>>(pos);
    k_hist<<<(EE + 255) / 256, 256>>>(ei);
    k_scan1<<<NB_SCAN, 1024>>>();
    k_scan2<<<1, 128>>>();
    k_fin<<<NB_SCAN, 1024>>>();
    k_scatter<<<(EE + 255) / 256, 256>>>(ei, pos);

    // ---- weight prep ----
    k_combine<<<129, 128>>>(nW2, lW1 + 0 * 132 * 128, nb2, 0);
    for (int l = 0; l < LL; l++)
        k_combine<<<129, 128>>>(lW2 + l * 128 * 128, gW1 + l * 128 * 128, lb2 + l * 128, 1 + l);
    k_split_all<<<NSLOT * 8, 256>>>(lW1, gW2);

    // ---- main chain ----
    // q = relu(x@nW1 + nb1) -> split pair 0
    k_gemm<16, 128, 1, true, true><<<GB, 256>>>(-1, x, nW1, nb1, 2, NN);
    // t0 = q@F0 + c0 -> buf1 (fp32)
    k_mmagemm<<<GT, 512, SM_BYTES>>>(0, 0, 1, NN);

    for (int l = 0; l < LL; l++) {
        const float* W1p = lW1 + l * 132 * 128 + 128 * 128;
        // r = gather(t=buf1) -> split pair 0
        k_gather<<<1184, 256>>>(W1p, lb1 + l * 128);
        if (l + 1 < LL) {
            // fused: u -> h -> t_{l+1} (buf1)
            k_layer<false><<<GT, 512, SM_BYTES>>>(1 + l, 4 + l, 7 + l, 1 + l,
                                                  gb1 + l * 128, gb2 + l * 128, NN);
        } else {
            // fused: u -> h (buf0)
            k_layer<true><<<GT, 512, SM_BYTES>>>(1 + l, 4 + l, 0, 1 + l,
                                                 gb1 + l * 128, gb2 + l * 128, NN);
        }
    }

    // head: buf0 -> buf2 -> buf1 -> out
    k_gemm<128, 64, 1, true, false><<<GB, 256>>>(0, nullptr, l1W, l1b, 2, NN);
    k_gemm<64, 16, 1, false, false><<<GB, 256>>>(2, nullptr, l2W, l2b, 1, NN);
    k_gout<<<GG, 256>>>(batch, out);
}

// round 14
// speedup vs baseline: 1.3145x; 1.0418x over previous
#include <cuda_runtime.h>
#include <cuda_bf16.h>
#include <math.h>
#include <stdint.h>

#define NN 100000
#define EE 1600000
#define HH 128
#define GG 256
#define LL 3
#define NB_SCAN ((NN + 1023) / 1024)   // 98
#define NTILES ((NN + 127) / 128)      // 782

#define RPITCH 272
#define TILE_U4 2176
#define HALF_B 34816
#define NSLOT 10

// ---------------- scratch ----------------
__device__ __align__(16) float g_h[NN * HH];
__device__ __align__(16) float g_t[NN * HH];
__device__ __align__(16) float g_tmp[NN * HH];
__device__ __align__(16) float g_F4[4][HH * HH];
__device__ __align__(16) float g_c4[5][HH];
__device__ __align__(16) uint4 g_Whi[NSLOT][TILE_U4];
__device__ __align__(16) uint4 g_Wlo[NSLOT][TILE_U4];
__device__ __align__(16) uint4 g_s0h[NN * 16];
__device__ __align__(16) uint4 g_s0l[NN * 16];
__device__ __align__(16) float4 g_nrm[NN];
__device__ int    g_deg[NN];
__device__ int    g_incl[NN];
__device__ int    g_rowptr[NN + 1];
__device__ int    g_cursor[NN];
__device__ int    g_srcs[EE];
__device__ float4 g_ppf[EE];
__device__ int    g_bsum[128];
__device__ int    g_is64;

__device__ __forceinline__ float* getbuf(int id) {
    switch (id) {
        case 0: return g_h;
        case 1: return g_t;
        default: return g_tmp;
    }
}

__device__ __forceinline__ int load_idx(const void* p, long long i, int is64) {
    if (is64) return (int)((const long long*)p)[i];
    return ((const int*)p)[i];
}

// ================= mma.sync + cp.async helpers =================
__device__ __forceinline__ uint32_t smem_u32(const void* p) {
    uint32_t a;
    asm("{ .reg .u64 t; cvta.to.shared.u64 t, %1; cvt.u32.u64 %0, t; }" : "=r"(a) : "l"(p));
    return a;
}
__device__ __forceinline__ void ldm4(uint32_t* r, uint32_t addr) {
    asm volatile("ldmatrix.sync.aligned.m8n8.x4.shared.b16 {%0,%1,%2,%3}, [%4];"
        : "=r"(r[0]), "=r"(r[1]), "=r"(r[2]), "=r"(r[3]) : "r"(addr));
}
__device__ __forceinline__ void mma16816(float* d, const uint32_t* a, uint32_t b0, uint32_t b1) {
    asm volatile("mma.sync.aligned.m16n8k16.row.col.f32.bf16.bf16.f32 "
        "{%0,%1,%2,%3}, {%4,%5,%6,%7}, {%8,%9}, {%0,%1,%2,%3};"
        : "+f"(d[0]), "+f"(d[1]), "+f"(d[2]), "+f"(d[3])
        : "r"(a[0]), "r"(a[1]), "r"(a[2]), "r"(a[3]), "r"(b0), "r"(b1));
}
__device__ __forceinline__ void cpa16(uint32_t dst, const void* src, unsigned sz) {
    asm volatile("cp.async.cg.shared.global [%0], [%1], 16, %2;"
        :: "r"(dst), "l"(src), "r"(sz) : "memory");
}
#define CPA_COMMIT() asm volatile("cp.async.commit_group;" ::: "memory")
#define CPA_WAIT(n)  asm volatile("cp.async.wait_group %0;" :: "n"(n) : "memory")

// split helpers
__device__ __forceinline__ void split1(float v, unsigned& h, unsigned& l) {
    __nv_bfloat16 hb = __float2bfloat16(v);
    float rem = v - __bfloat162float(hb);
    __nv_bfloat16 lb = __float2bfloat16(rem);
    h = (unsigned)__bfloat16_as_ushort(hb);
    l = (unsigned)__bfloat16_as_ushort(lb);
}
__device__ __forceinline__ void split8(const float* v, uint4& hi, uint4& lo) {
    unsigned hs[8], ls[8];
#pragma unroll
    for (int j = 0; j < 8; j++) split1(v[j], hs[j], ls[j]);
    hi = make_uint4(hs[0] | (hs[1] << 16), hs[2] | (hs[3] << 16), hs[4] | (hs[5] << 16), hs[6] | (hs[7] << 16));
    lo = make_uint4(ls[0] | (ls[1] << 16), ls[2] | (ls[3] << 16), ls[4] | (ls[5] << 16), ls[6] | (ls[7] << 16));
}
__device__ __forceinline__ void split4_u2(const float4& v, uint2& hi, uint2& lo) {
    unsigned h0, h1, h2, h3, l0, l1, l2, l3;
    split1(v.x, h0, l0); split1(v.y, h1, l1); split1(v.z, h2, l2); split1(v.w, h3, l3);
    hi = make_uint2(h0 | (h1 << 16), h2 | (h3 << 16));
    lo = make_uint2(l0 | (l1 << 16), l2 | (l3 << 16));
}

// MMA over one 128x128 tile
__device__ __forceinline__ void mma_tile(float d[8][4], uint32_t aH, uint32_t aL,
                                         uint32_t bH, uint32_t bL,
                                         int mrow0, int ncol0, int lane) {
    const int lrow = lane & 15;
    const int lkof = ((lane >> 4) << 3) * 2;
#pragma unroll
    for (int nt = 0; nt < 8; nt++)
#pragma unroll
        for (int j = 0; j < 4; j++) d[nt][j] = 0.f;
#pragma unroll
    for (int kk = 0; kk < 8; kk++) {
        int kb = kk * 32 + lkof;
        uint32_t ah[4], al[4];
        {
            uint32_t off = (mrow0 + lrow) * RPITCH + kb;
            ldm4(ah, aH + off);
            ldm4(al, aL + off);
        }
        uint32_t bh[4][4], bl[4][4];
#pragma unroll
        for (int np = 0; np < 4; np++) {
            uint32_t off = (ncol0 + np * 16 + lrow) * RPITCH + kb;
            ldm4(bh[np], bH + off);
            ldm4(bl[np], bL + off);
        }
#pragma unroll
        for (int np = 0; np < 4; np++) {
            mma16816(d[np * 2],     ah, bh[np][0], bh[np][2]);
            mma16816(d[np * 2],     ah, bl[np][0], bl[np][2]);
            mma16816(d[np * 2],     al, bh[np][0], bh[np][2]);
            mma16816(d[np * 2 + 1], ah, bh[np][1], bh[np][3]);
            mma16816(d[np * 2 + 1], ah, bl[np][1], bl[np][3]);
            mma16816(d[np * 2 + 1], al, bh[np][1], bh[np][3]);
        }
    }
}

// ---------------- CSR-side kernels ----------------
__global__ void k_detect(const void* ei) {
    __shared__ int s_nz;
    if (threadIdx.x == 0) s_nz = 0;
    __syncthreads();
    const int* w = (const int*)ei;
    int v = w[2 * threadIdx.x + 1];
    int v2 = w[2 * (threadIdx.x + 1024) + 1];
    if ((v | v2) != 0) atomicOr(&s_nz, 1);
    __syncthreads();
    if (threadIdx.x == 0) g_is64 = s_nz ? 0 : 1;
}

__global__ void k_init(const float* pos) {
    int i = blockIdx.x * blockDim.x + threadIdx.x;
    if (i < NN) {
        g_deg[i] = 0;
        float px = pos[3 * i], py = pos[3 * i + 1], pz = pos[3 * i + 2];
        float n = sqrtf(px * px + py * py + pz * pz) + 1e-12f;
        g_nrm[i] = make_float4(px / n, py / n, pz / n, 0.f);
    }
}

__global__ void k_hist(const void* ei) {
    int e = blockIdx.x * blockDim.x + threadIdx.x;
    if (e < EE) {
        int d = load_idx(ei, (long long)EE + e, g_is64);
        atomicAdd(&g_deg[d], 1);
    }
}

__global__ void k_scan1() {
    __shared__ int s[1024];
    int tid = threadIdx.x;
    int i = blockIdx.x * 1024 + tid;
    int v = (i < NN) ? g_deg[i] : 0;
    s[tid] = v;
    __syncthreads();
    for (int off = 1; off < 1024; off <<= 1) {
        int a = (tid >= off) ? s[tid - off] : 0;
        __syncthreads();
        s[tid] += a;
        __syncthreads();
    }
    if (i < NN) g_incl[i] = s[tid];
    if (tid == 1023) g_bsum[blockIdx.x] = s[1023];
}

__global__ void k_scan2() {
    __shared__ int s[128];
    int tid = threadIdx.x;
    s[tid] = (tid < NB_SCAN) ? g_bsum[tid] : 0;
    __syncthreads();
    for (int off = 1; off < 128; off <<= 1) {
        int a = (tid >= off) ? s[tid - off] : 0;
        __syncthreads();
        s[tid] += a;
        __syncthreads();
    }
    if (tid < NB_SCAN) g_bsum[tid] = s[tid];
}

__global__ void k_fin() {
    int tid = threadIdx.x;
    int i = blockIdx.x * 1024 + tid;
    if (i < NN) {
        int off = blockIdx.x ? g_bsum[blockIdx.x - 1] : 0;
        int excl = g_incl[i] - g_deg[i] + off;
        g_rowptr[i] = excl;
        g_cursor[i] = excl;
    }
    if (i == 0) g_rowptr[NN] = EE;
}

__device__ __forceinline__ float dot3(float ax, float ay, float az, float bx, float by, float bz) {
    return ax * bx + ay * by + az * bz;
}
__device__ __forceinline__ float crossnorm(float ax, float ay, float az, float bx, float by, float bz) {
    float cx = ay * bz - az * by;
    float cy = az * bx - ax * bz;
    float cz = ax * by - ay * bx;
    return sqrtf(cx * cx + cy * cy + cz * cz);
}

__global__ void k_scatter(const void* ei, const float* pos) {
    int e = blockIdx.x * blockDim.x + threadIdx.x;
    if (e >= EE) return;
    int is64 = g_is64;
    int s = load_idx(ei, e, is64);
    int d = load_idx(ei, (long long)EE + e, is64);
    float pix = pos[3 * d], piy = pos[3 * d + 1], piz = pos[3 * d + 2];
    float pjx = pos[3 * s], pjy = pos[3 * s + 1], pjz = pos[3 * s + 2];
    float4 ni = g_nrm[d];
    float4 nj = g_nrm[s];
    float dx = pjx - pix, dy = pjy - piy, dz = pjz - piz;
    float f0 = sqrtf(dx * dx + dy * dy + dz * dz);
    float f1 = atan2f(crossnorm(ni.x, ni.y, ni.z, dx, dy, dz), dot3(ni.x, ni.y, ni.z, dx, dy, dz));
    float f2 = atan2f(crossnorm(nj.x, nj.y, nj.z, dx, dy, dz), dot3(nj.x, nj.y, nj.z, dx, dy, dz));
    float f3 = atan2f(crossnorm(ni.x, ni.y, ni.z, nj.x, nj.y, nj.z), dot3(ni.x, ni.y, ni.z, nj.x, nj.y, nj.z));
    int slot = atomicAdd(&g_cursor[d], 1);
    g_srcs[slot] = s;
    g_ppf[slot] = make_float4(f0, f1, f2, f3);
}

// ---------------- weight prep ----------------
__global__ void k_combine(const float* A, const float* B, const float* v, int fidx) {
    int col = threadIdx.x;
    int row = blockIdx.x;
    if (row < 128) {
        float s = 0.f;
        for (int k = 0; k < 128; k++) s = fmaf(A[row * 128 + k], B[k * 128 + col], s);
        g_F4[fidx][row * 128 + col] = s;
    } else {
        float s = 0.f;
        for (int k = 0; k < 128; k++) s = fmaf(v[k], B[k * 128 + col], s);
        g_c4[fidx][col] = s;
    }
}

// slots: 0 = F0; 1..3 = F_{1+l}; 4..6 = gW2_l; 7..8 = W1h_{l+1}; 9 = l1W padded
__global__ void k_split_all(const float* lW1, const float* gW2,
                            const float* l1W, const float* l1b) {
    int g = blockIdx.x;
    int slot = g >> 3;
    int i = (g & 7) * 256 + threadIdx.x;
    int n = i >> 4, kg = i & 15;
    float v[8];
    if (slot == 9) {
#pragma unroll
        for (int j = 0; j < 8; j++) v[j] = (n < 64) ? l1W[(kg * 8 + j) * 64 + n] : 0.f;
        if ((g & 7) == 0 && threadIdx.x < 128)
            g_c4[4][threadIdx.x] = (threadIdx.x < 64) ? l1b[threadIdx.x] : 0.f;
    } else {
        const float* src;
        if (slot <= 3) src = g_F4[slot];
        else if (slot <= 6) src = gW2 + (slot - 4) * 128 * 128;
        else src = lW1 + (slot - 6) * 132 * 128;
#pragma unroll
        for (int j = 0; j < 8; j++) v[j] = src[(kg * 8 + j) * 128 + n];
    }
    uint4 hi, lo;
    split8(v, hi, lo);
    g_Whi[slot][n * 17 + kg] = hi;
    g_Wlo[slot][n * 17 + kg] = lo;
}

__device__ __forceinline__ void issue_copy512(uint32_t aH, uint32_t aL,
                                              const uint4* Xhi, const uint4* Xlo,
                                              int row0, int nrows, int tid) {
#pragma unroll
    for (int i = tid; i < 2048; i += 512) {
        int row = i >> 4, grp = i & 15;
        int r = row0 + row;
        unsigned sz = (r < nrows) ? 16u : 0u;
        long long rc = (r < nrows) ? r : 0;
        uint32_t off = (uint32_t)(row * RPITCH + grp * 16);
        cpa16(aH + off, &Xhi[rc * 16 + grp], sz);
        cpa16(aL + off, &Xlo[rc * 16 + grp], sz);
    }
}

__device__ __forceinline__ void copy_w(uint32_t dH, uint32_t dL, int slot, int tid) {
    const uint4* sh = g_Whi[slot];
    const uint4* sl = g_Wlo[slot];
    for (int i = tid; i < TILE_U4; i += 512) {
        cpa16(dH + (uint32_t)(i * 16), &sh[i], 16u);
        cpa16(dL + (uint32_t)(i * 16), &sl[i], 16u);
    }
}

// ---------------- pipelined single-GEMM (t0 + head1) ----------------
#define SM_BHI 0
#define SM_A0 69632
#define SM_A1 139264
#define SM_BYTES 208896

template <bool RELU>
__global__ void __launch_bounds__(512, 1) k_mmagemm(int wslot, int cidx, int yid, int nrows) {
    extern __shared__ char sm[];
    const uint4* Xhi = g_s0h;
    const uint4* Xlo = g_s0l;
    float* Y = getbuf(yid);
    const float* cvec = g_c4[cidx];

    int tid = threadIdx.x;
    int wid = tid >> 5;
    int lane = tid & 31;

    uint4* bhi_s = (uint4*)(sm + SM_BHI);
    uint4* blo_s = (uint4*)(sm + SM_BHI + HALF_B);
    for (int i = tid; i < TILE_U4; i += 512) {
        bhi_s[i] = g_Whi[wslot][i];
        blo_s[i] = g_Wlo[wslot][i];
    }

    const int mrow0 = (wid & 7) * 16;
    const int ncol0 = (wid >> 3) * 64;

    uint32_t a0h = smem_u32(sm + SM_A0), a0l = a0h + HALF_B;
    uint32_t a1h = smem_u32(sm + SM_A1), a1l = a1h + HALF_B;
    uint32_t bH = smem_u32(sm + SM_BHI), bL = bH + HALF_B;

    int tile0 = blockIdx.x;
    if (tile0 < NTILES) {
        issue_copy512(a0h, a0l, Xhi, Xlo, tile0 * 128, nrows, tid);
        CPA_COMMIT();
    }

    int it = 0;
    for (int tile = tile0; tile < NTILES; tile += gridDim.x, it++) {
        int par = it & 1;
        uint32_t aH = par ? a1h : a0h;
        uint32_t aL = par ? a1l : a0l;
        int nxt = tile + gridDim.x;
        if (nxt < NTILES) {
            issue_copy512(par ? a0h : a1h, par ? a0l : a1l, Xhi, Xlo, nxt * 128, nrows, tid);
            CPA_COMMIT();
            CPA_WAIT(1);
        } else {
            CPA_WAIT(0);
        }
        __syncthreads();

        int row0 = tile * 128;
        float d[8][4];
        mma_tile(d, aH, aL, bH, bL, mrow0, ncol0, lane);

        int r0 = row0 + mrow0 + (lane >> 2);
        int r1 = r0 + 8;
        int cbase = ncol0 + 2 * (lane & 3);
#pragma unroll
        for (int nt = 0; nt < 8; nt++) {
            int c = cbase + nt * 8;
            float b0 = cvec[c], b1 = cvec[c + 1];
            if (r0 < nrows) {
                float v0 = d[nt][0] + b0, v1 = d[nt][1] + b1;
                if (RELU) { v0 = fmaxf(v0, 0.f); v1 = fmaxf(v1, 0.f); }
                *(float2*)&Y[(long long)r0 * 128 + c] = make_float2(v0, v1);
            }
            if (r1 < nrows) {
                float v2 = d[nt][2] + b0, v3 = d[nt][3] + b1;
                if (RELU) { v2 = fmaxf(v2, 0.f); v3 = fmaxf(v3, 0.f); }
                *(float2*)&Y[(long long)r1 * 128 + c] = make_float2(v2, v3);
            }
        }
        __syncthreads();
    }
}

// ---------------- fused layer kernel: u -> h -> (t | h split out) ----------------
template <bool LAST>
__global__ void __launch_bounds__(512, 1) k_layer(int ws1, int ws2, int ws3, int cidx,
                                                  const float* gb1, const float* gb2, int nrows) {
    extern __shared__ char sm[];
    const uint4* Xhi = g_s0h;
    const uint4* Xlo = g_s0l;
    ushort2* Ohi = (ushort2*)g_s0h;
    ushort2* Olo = (ushort2*)g_s0l;
    const float* cvec = g_c4[cidx];

    int tid = threadIdx.x;
    int wid = tid >> 5;
    int lane = tid & 31;
    const int mrow0 = (wid & 7) * 16;
    const int ncol0 = (wid >> 3) * 64;

    uint32_t R0h = smem_u32(sm),   R0l = R0h + HALF_B;
    uint32_t R1h = R0h + 69632,    R1l = R1h + HALF_B;
    uint32_t R2h = R0h + 139264,   R2l = R2h + HALF_B;

    for (int tile = blockIdx.x; tile < NTILES; tile += gridDim.x) {
        int row0 = tile * 128;
        issue_copy512(R0h, R0l, Xhi, Xlo, row0, nrows, tid);
        copy_w(R1h, R1l, ws1, tid);
        CPA_COMMIT();
        CPA_WAIT(0);
        __syncthreads();

        // MMA1: u-pre = r@F
        float d[8][4];
        mma_tile(d, R0h, R0l, R1h, R1l, mrow0, ncol0, lane);
        __syncthreads();

        copy_w(R0h, R0l, ws2, tid);
        if (!LAST) copy_w(R1h, R1l, ws3, tid);
        CPA_COMMIT();

        int lr0 = mrow0 + (lane >> 2);
        int lr1 = lr0 + 8;
        int gr0 = row0 + lr0, gr1 = row0 + lr1;
        float sc0 = (gr0 < nrows) ? (float)g_deg[gr0] : 0.f;
        float sc1 = (gr1 < nrows) ? (float)g_deg[gr1] : 0.f;
        int cbase = ncol0 + 2 * (lane & 3);
#pragma unroll
        for (int nt = 0; nt < 8; nt++) {
            int c = cbase + nt * 8;
            float b0 = gb1[c], b1 = gb1[c + 1];
            float c0 = cvec[c], c1 = cvec[c + 1];
            float u0 = fmaxf(d[nt][0] + b0 + sc0 * c0, 0.f);
            float u1 = fmaxf(d[nt][1] + b1 + sc0 * c1, 0.f);
            float u2 = fmaxf(d[nt][2] + b0 + sc1 * c0, 0.f);
            float u3 = fmaxf(d[nt][3] + b1 + sc1 * c1, 0.f);
            unsigned h0, h1, h2, h3, l0, l1, l2, l3;
            split1(u0, h0, l0); split1(u1, h1, l1);
            split1(u2, h2, l2); split1(u3, h3, l3);
            uint32_t off0 = lr0 * RPITCH + c * 2;
            uint32_t off1 = lr1 * RPITCH + c * 2;
            *(ushort2*)(sm + 139264 + off0) = make_ushort2((unsigned short)h0, (unsigned short)h1);
            *(ushort2*)(sm + 139264 + HALF_B + off0) = make_ushort2((unsigned short)l0, (unsigned short)l1);
            *(ushort2*)(sm + 139264 + off1) = make_ushort2((unsigned short)h2, (unsigned short)h3);
            *(ushort2*)(sm + 139264 + HALF_B + off1) = make_ushort2((unsigned short)l2, (unsigned short)l3);
        }
        CPA_WAIT(0);
        __syncthreads();

        // MMA2: h-pre = u@W2
        mma_tile(d, R2h, R2l, R0h, R0l, mrow0, ncol0, lane);
        __syncthreads();

        if (LAST) {
            // h epilogue -> split pair 0 (overwrites this tile's rows of r; safe)
#pragma unroll
            for (int nt = 0; nt < 8; nt++) {
                int c = cbase + nt * 8;
                float b0 = gb2[c], b1 = gb2[c + 1];
                if (gr0 < nrows) {
                    float v0 = fmaxf(d[nt][0] + b0, 0.f);
                    float v1 = fmaxf(d[nt][1] + b1, 0.f);
                    unsigned h0, h1, l0, l1;
                    split1(v0, h0, l0); split1(v1, h1, l1);
                    long long idx = (long long)gr0 * 64 + (c >> 1);
                    Ohi[idx] = make_ushort2((unsigned short)h0, (unsigned short)h1);
                    Olo[idx] = make_ushort2((unsigned short)l0, (unsigned short)l1);
                }
                if (gr1 < nrows) {
                    float v2 = fmaxf(d[nt][2] + b0, 0.f);
                    float v3 = fmaxf(d[nt][3] + b1, 0.f);
                    unsigned h2, h3, l2, l3;
                    split1(v2, h2, l2); split1(v3, h3, l3);
                    long long idx = (long long)gr1 * 64 + (c >> 1);
                    Ohi[idx] = make_ushort2((unsigned short)h2, (unsigned short)h3);
                    Olo[idx] = make_ushort2((unsigned short)l2, (unsigned short)l3);
                }
            }
        } else {
            // h epilogue -> R2 (split)
#pragma unroll
            for (int nt = 0; nt < 8; nt++) {
                int c = cbase + nt * 8;
                float b0 = gb2[c], b1 = gb2[c + 1];
                float v0 = fmaxf(d[nt][0] + b0, 0.f);
                float v1 = fmaxf(d[nt][1] + b1, 0.f);
                float v2 = fmaxf(d[nt][2] + b0, 0.f);
                float v3 = fmaxf(d[nt][3] + b1, 0.f);
                unsigned h0, h1, h2, h3, l0, l1, l2, l3;
                split1(v0, h0, l0); split1(v1, h1, l1);
                split1(v2, h2, l2); split1(v3, h3, l3);
                uint32_t off0 = lr0 * RPITCH + c * 2;
                uint32_t off1 = lr1 * RPITCH + c * 2;
                *(ushort2*)(sm + 139264 + off0) = make_ushort2((unsigned short)h0, (unsigned short)h1);
                *(ushort2*)(sm + 139264 + HALF_B + off0) = make_ushort2((unsigned short)l0, (unsigned short)l1);
                *(ushort2*)(sm + 139264 + off1) = make_ushort2((unsigned short)h2, (unsigned short)h3);
                *(ushort2*)(sm + 139264 + HALF_B + off1) = make_ushort2((unsigned short)l2, (unsigned short)l3);
            }
            __syncthreads();

            // MMA3: t = h@W1h
            mma_tile(d, R2h, R2l, R1h, R1l, mrow0, ncol0, lane);
#pragma unroll
            for (int nt = 0; nt < 8; nt++) {
                int c = cbase + nt * 8;
                if (gr0 < nrows)
                    *(float2*)&g_t[(long long)gr0 * 128 + c] = make_float2(d[nt][0], d[nt][1]);
                if (gr1 < nrows)
                    *(float2*)&g_t[(long long)gr1 * 128 + c] = make_float2(d[nt][2], d[nt][3]);
            }
        }
        __syncthreads();
    }
}

// ---------------- small GEMM; XPITCH = input row pitch ----------------
template <int K, int M, int BMODE, bool RELU, bool OSPLIT, int XPITCH>
__global__ void k_gemm(int xid, const float* Xext,
                       const float* W, const float* bias,
                       int yid, int nrows) {
    constexpr int NT = 64;
    constexpr int CG = M / 4;
    constexpr int NG = 256 / CG;
    constexpr int NPT = NT / NG;
    constexpr int KC = 16;
    __shared__ float Ws[KC * M];
    __shared__ float Xs[NT * K];

    const float* X = (xid >= 0) ? getbuf(xid) : Xext;
    float* Y = getbuf(yid);
    uint2* Ohi = (uint2*)g_s0h;
    uint2* Olo = (uint2*)g_s0l;

    int tid = threadIdx.x;
    const int c = tid % CG;
    const int g = tid / CG;
    const float4* Ws4 = (const float4*)Ws;
    int ntiles = (nrows + NT - 1) / NT;

    for (int tile = blockIdx.x; tile < ntiles; tile += gridDim.x) {
        int row0 = tile * NT;
        __syncthreads();
        for (int i = tid; i < NT * K; i += 256) {
            int rr = i / K, kk = i % K;
            int r = row0 + rr;
            Xs[i] = (r < nrows) ? X[(long long)r * XPITCH + kk] : 0.f;
        }
        float4 acc[NPT];
#pragma unroll
        for (int r = 0; r < NPT; r++) acc[r] = make_float4(0.f, 0.f, 0.f, 0.f);

        for (int kc0 = 0; kc0 < K; kc0 += KC) {
            __syncthreads();
            for (int i = tid; i < KC * M; i += 256) Ws[i] = W[kc0 * M + i];
            __syncthreads();
#pragma unroll
            for (int k = 0; k < KC; k++) {
                float4 w = Ws4[k * CG + c];
#pragma unroll
                for (int r = 0; r < NPT; r++) {
                    float xv = Xs[(g * NPT + r) * K + kc0 + k];
                    acc[r].x = fmaf(xv, w.x, acc[r].x);
                    acc[r].y = fmaf(xv, w.y, acc[r].y);
                    acc[r].z = fmaf(xv, w.z, acc[r].z);
                    acc[r].w = fmaf(xv, w.w, acc[r].w);
                }
            }
        }
        float4 bv = make_float4(0.f, 0.f, 0.f, 0.f);
        if (BMODE >= 1) bv = ((const float4*)bias)[c];
#pragma unroll
        for (int r = 0; r < NPT; r++) {
            int row = row0 + g * NPT + r;
            if (row < nrows) {
                float4 v;
                v.x = acc[r].x + bv.x;
                v.y = acc[r].y + bv.y;
                v.z = acc[r].z + bv.z;
                v.w = acc[r].w + bv.w;
                if (RELU) {
                    v.x = fmaxf(v.x, 0.f);
                    v.y = fmaxf(v.y, 0.f);
                    v.z = fmaxf(v.z, 0.f);
                    v.w = fmaxf(v.w, 0.f);
                }
                if (OSPLIT) {
                    uint2 hi, lo;
                    split4_u2(v, hi, lo);
                    Ohi[(long long)row * (M / 4) + c] = hi;
                    Olo[(long long)row * (M / 4) + c] = lo;
                } else {
                    ((float4*)Y)[(long long)row * CG + c] = v;
                }
            }
        }
    }
}

// ---------------- edge gather: split output into pair 0 ----------------
__global__ void k_gather(const float* W1p, const float* b1) {
    int lane = threadIdx.x & 31;
    int wid = (blockIdx.x * blockDim.x + threadIdx.x) >> 5;
    int nwarps = (gridDim.x * blockDim.x) >> 5;
    const float4* W4 = (const float4*)W1p;
    float4 w0 = W4[0 * 32 + lane];
    float4 w1 = W4[1 * 32 + lane];
    float4 w2 = W4[2 * 32 + lane];
    float4 w3 = W4[3 * 32 + lane];
    float4 bb = ((const float4*)b1)[lane];
    const float4* t4 = (const float4*)g_t;
    uint2* Ohi = (uint2*)g_s0h;
    uint2* Olo = (uint2*)g_s0l;
    for (int node = wid; node < NN; node += nwarps) {
        int s0 = g_rowptr[node];
        int s1 = g_rowptr[node + 1];
        float4 acc = make_float4(0.f, 0.f, 0.f, 0.f);
        for (int s = s0; s < s1; s++) {
            int src = __ldg(&g_srcs[s]);
            float4 pf = __ldg(&g_ppf[s]);
            float4 tv = __ldg(&t4[(long long)src * 32 + lane]);
            float4 h;
            h.x = bb.x + tv.x;
            h.y = bb.y + tv.y;
            h.z = bb.z + tv.z;
            h.w = bb.w + tv.w;
            h.x = fmaf(pf.x, w0.x, h.x); h.y = fmaf(pf.x, w0.y, h.y); h.z = fmaf(pf.x, w0.z, h.z); h.w = fmaf(pf.x, w0.w, h.w);
            h.x = fmaf(pf.y, w1.x, h.x); h.y = fmaf(pf.y, w1.y, h.y); h.z = fmaf(pf.y, w1.z, h.z); h.w = fmaf(pf.y, w1.w, h.w);
            h.x = fmaf(pf.z, w2.x, h.x); h.y = fmaf(pf.z, w2.y, h.y); h.z = fmaf(pf.z, w2.z, h.z); h.w = fmaf(pf.z, w2.w, h.w);
            h.x = fmaf(pf.w, w3.x, h.x); h.y = fmaf(pf.w, w3.y, h.y); h.z = fmaf(pf.w, w3.z, h.z); h.w = fmaf(pf.w, w3.w, h.w);
            acc.x += fmaxf(h.x, 0.f);
            acc.y += fmaxf(h.y, 0.f);
            acc.z += fmaxf(h.z, 0.f);
            acc.w += fmaxf(h.w, 0.f);
        }
        uint2 hi, lo;
        split4_u2(acc, hi, lo);
        Ohi[(long long)node * 32 + lane] = hi;
        Olo[(long long)node * 32 + lane] = lo;
    }
}

// ---------------- per-graph reduction ----------------
__global__ void k_gout(const void* batch, float* out) {
    int g = blockIdx.x;
    int is64 = g_is64;
    int lo = 0, hi = NN;
    while (lo < hi) { int m = (lo + hi) >> 1; if (load_idx(batch, m, is64) < g) lo = m + 1; else hi = m; }
    int start = lo;
    int lo2 = start, hi2 = NN;
    while (lo2 < hi2) { int m = (lo2 + hi2) >> 1; if (load_idx(batch, m, is64) < g + 1) lo2 = m + 1; else hi2 = m; }
    int end = lo2;
    int tid = threadIdx.x, col = tid & 15, gy = tid >> 4;
    float s = 0.f;
    for (int n = start + gy; n < end; n += 16) s += g_t[(long long)n * 16 + col];
    __shared__ float sm[16][16];
    sm[gy][col] = s;
    __syncthreads();
    if (gy == 0) {
        float tot = 0.f;
#pragma unroll
        for (int k = 0; k < 16; k++) tot += sm[k][col];
        out[g * 16 + col] = tot;
    }
}

// ---------------- launch ----------------
extern "C" void kernel_launch(void* const* d_in, const int* in_sizes, int n_in,
                              void* d_out, int out_size) {
    const float* x     = (const float*)d_in[0];
    const float* pos   = (const float*)d_in[1];
    const void*  ei    = d_in[2];
    const void*  batch = d_in[3];
    const float* nW1 = (const float*)d_in[4];
    const float* nb1 = (const float*)d_in[5];
    const float* nW2 = (const float*)d_in[6];
    const float* nb2 = (const float*)d_in[7];
    const float* lW1 = (const float*)d_in[8];
    const float* lb1 = (const float*)d_in[9];
    const float* lW2 = (const float*)d_in[10];
    const float* lb2 = (const float*)d_in[11];
    const float* gW1 = (const float*)d_in[12];
    const float* gb1 = (const float*)d_in[13];
    const float* gW2 = (const float*)d_in[14];
    const float* gb2 = (const float*)d_in[15];
    const float* l1W = (const float*)d_in[16];
    const float* l1b = (const float*)d_in[17];
    const float* l2W = (const float*)d_in[18];
    const float* l2b = (const float*)d_in[19];
    float* out = (float*)d_out;

    // lazily-created side stream + fork/join events (host objects, created once)
    static cudaStream_t s1 = nullptr;
    static cudaEvent_t evF = nullptr, evJ = nullptr;
    if (s1 == nullptr) {
        cudaStreamCreateWithFlags(&s1, cudaStreamNonBlocking);
        cudaEventCreateWithFlags(&evF, cudaEventDisableTiming);
        cudaEventCreateWithFlags(&evJ, cudaEventDisableTiming);
    }

    cudaFuncSetAttribute(k_mmagemm<false>, cudaFuncAttributeMaxDynamicSharedMemorySize, SM_BYTES);
    cudaFuncSetAttribute(k_mmagemm<true>,  cudaFuncAttributeMaxDynamicSharedMemorySize, SM_BYTES);
    cudaFuncSetAttribute(k_layer<false>,   cudaFuncAttributeMaxDynamicSharedMemorySize, SM_BYTES);
    cudaFuncSetAttribute(k_layer<true>,    cudaFuncAttributeMaxDynamicSharedMemorySize, SM_BYTES);

    const int GB = 296;
    const int GT = 148;

    // ---- fork: CSR chain on side stream ----
    cudaEventRecord(evF, 0);
    cudaStreamWaitEvent(s1, evF, 0);
    k_detect<<<1, 1024, 0, s1>>>(ei);
    k_init<<<(NN + 255) / 256, 256, 0, s1>>>(pos);
    k_hist<<<(EE + 255) / 256, 256, 0, s1>>>(ei);
    k_scan1<<<NB_SCAN, 1024, 0, s1>>>();
    k_scan2<<<1, 128, 0, s1>>>();
    k_fin<<<NB_SCAN, 1024, 0, s1>>>();
    k_scatter<<<(EE + 255) / 256, 256, 0, s1>>>(ei, pos);
    cudaEventRecord(evJ, s1);

    // ---- main stream: weight prep + q + t0 (independent of CSR) ----
    k_combine<<<129, 128>>>(nW2, lW1 + 0 * 132 * 128, nb2, 0);
    for (int l = 0; l < LL; l++)
        k_combine<<<129, 128>>>(lW2 + l * 128 * 128, gW1 + l * 128 * 128, lb2 + l * 128, 1 + l);
    k_split_all<<<NSLOT * 8, 256>>>(lW1, gW2, l1W, l1b);

    // q = relu(x@nW1 + nb1) -> split pair 0
    k_gemm<16, 128, 1, true, true, 16><<<GB, 256>>>(-1, x, nW1, nb1, 2, NN);
    // t0 = q@F0 + c0 -> buf1 (fp32)
    k_mmagemm<false><<<GT, 512, SM_BYTES>>>(0, 0, 1, NN);

    // ---- join: first gather needs CSR + t0 ----
    cudaStreamWaitEvent(0, evJ, 0);

    for (int l = 0; l < LL; l++) {
        const float* W1p = lW1 + l * 132 * 128 + 128 * 128;
        k_gather<<<1184, 256>>>(W1p, lb1 + l * 128);
        if (l + 1 < LL) {
            k_layer<false><<<GT, 512, SM_BYTES>>>(1 + l, 4 + l, 7 + l, 1 + l,
                                                  gb1 + l * 128, gb2 + l * 128, NN);
        } else {
            k_layer<true><<<GT, 512, SM_BYTES>>>(1 + l, 4 + l, 0, 1 + l,
                                                 gb1 + l * 128, gb2 + l * 128, NN);
        }
    }

    // head1 (tensor path, padded l1W): reads h split pair0 -> buf2 (128-pitch, lower 64 valid)
    k_mmagemm<true><<<GT, 512, SM_BYTES>>>(9, 4, 2, NN);
    // head2: buf2 (pitch 128, K=64) -> buf1 (N x 16)
    k_gemm<64, 16, 1, false, false, 128><<<GB, 256>>>(2, nullptr, l2W, l2b, 1, NN);
    k_gout<<<GG, 256>>>(batch, out);
}